// round 10
// baseline (speedup 1.0000x reference)
#include <cuda_runtime.h>
#include <cuda_bf16.h>
#include <math.h>
#include <stdint.h>

#define D_MODEL 1024
#define NHEADS  16
#define DH      64
#define SEQ     2048
#define BATCH   2
#define WIN     128
#define MROWS   (BATCH * SEQ)   // 4096

// ---------------- scratch (static device memory) ----------------
__device__ float g_q [MROWS * D_MODEL];
__device__ float g_k [MROWS * D_MODEL];
__device__ float g_v [MROWS * D_MODEL];

__device__ __nv_bfloat16 g_xh [MROWS * D_MODEL];
__device__ __nv_bfloat16 g_xl [MROWS * D_MODEL];
__device__ __nv_bfloat16 g_wh [4 * D_MODEL * D_MODEL];
__device__ __nv_bfloat16 g_wl [4 * D_MODEL * D_MODEL];
__device__ __nv_bfloat16 g_aoh[MROWS * D_MODEL];
__device__ __nv_bfloat16 g_aol[MROWS * D_MODEL];

// ---------------- PTX helpers ----------------
__device__ __forceinline__ uint32_t smem_u32(const void* p) {
    uint32_t a;
    asm("{ .reg .u64 t; cvta.to.shared.u64 t, %1; cvt.u32.u64 %0, t; }"
        : "=r"(a) : "l"(p));
    return a;
}
#define CPA16(dst, src) \
    asm volatile("cp.async.cg.shared.global [%0], [%1], 16;" :: "r"(dst), "l"(src))
#define CPA_COMMIT() asm volatile("cp.async.commit_group;" ::: "memory")
#define CPA_WAIT1()  asm volatile("cp.async.wait_group 1;" ::: "memory")
#define CPA_WAIT0()  asm volatile("cp.async.wait_group 0;" ::: "memory")

#define LDM4(r, addr) \
    asm volatile("ldmatrix.sync.aligned.m8n8.x4.shared.b16 {%0,%1,%2,%3}, [%4];" \
        : "=r"((r)[0]), "=r"((r)[1]), "=r"((r)[2]), "=r"((r)[3]) : "r"(addr))

#define LDM4T(r, addr) \
    asm volatile("ldmatrix.sync.aligned.m8n8.x4.trans.shared.b16 {%0,%1,%2,%3}, [%4];" \
        : "=r"((r)[0]), "=r"((r)[1]), "=r"((r)[2]), "=r"((r)[3]) : "r"(addr))

#define MMA16816(acc, a, b0, b1) \
    asm volatile("mma.sync.aligned.m16n8k16.row.col.f32.bf16.bf16.f32 " \
        "{%0,%1,%2,%3}, {%4,%5,%6,%7}, {%8,%9}, {%0,%1,%2,%3};" \
        : "+f"((acc)[0]), "+f"((acc)[1]), "+f"((acc)[2]), "+f"((acc)[3]) \
        : "r"((a)[0]), "r"((a)[1]), "r"((a)[2]), "r"((a)[3]), "r"(b0), "r"(b1))

__device__ __forceinline__ void split2(float x, float y, uint32_t& oh, uint32_t& ol) {
    __nv_bfloat16 hx = __float2bfloat16(x), hy = __float2bfloat16(y);
    __nv_bfloat162 th; th.x = hx; th.y = hy;
    __nv_bfloat162 tl;
    tl.x = __float2bfloat16(x - __bfloat162float(hx));
    tl.y = __float2bfloat16(y - __bfloat162float(hy));
    oh = *(uint32_t*)&th; ol = *(uint32_t*)&tl;
}

// ---------------------------------------------------------------------------
// fp32 -> bf16 hi/lo split, all inputs in one launch.
// ---------------------------------------------------------------------------
__global__ __launch_bounds__(256)
void conv_all(const float* __restrict__ x,
              const float* __restrict__ Wq, const float* __restrict__ Wk,
              const float* __restrict__ Wv, const float* __restrict__ Wo)
{
    int blk = blockIdx.x;
    const float* src;
    __nv_bfloat16 *hi, *lo;
    int i;
    if (blk < 4096) {
        src = x; hi = g_xh; lo = g_xl;
        i = blk * 256 + threadIdx.x;
    } else {
        int w  = (blk - 4096) >> 10;
        int bb = (blk - 4096) & 1023;
        src = (w == 0) ? Wq : (w == 1) ? Wk : (w == 2) ? Wv : Wo;
        hi = g_wh + (size_t)w * D_MODEL * D_MODEL;
        lo = g_wl + (size_t)w * D_MODEL * D_MODEL;
        i = bb * 256 + threadIdx.x;
    }

    float4 v = ((const float4*)src)[i];
    uint32_t h01, l01, h23, l23;
    split2(v.x, v.y, h01, l01);
    split2(v.z, v.w, h23, l23);
    ((uint32_t*)hi)[i * 2]     = h01;
    ((uint32_t*)hi)[i * 2 + 1] = h23;
    ((uint32_t*)lo)[i * 2]     = l01;
    ((uint32_t*)lo)[i * 2 + 1] = l23;
}

// ---------------------------------------------------------------------------
// mma.sync bf16-split GEMM: C = A*W^T + bias.
// R10: 128(M) x 64(N) CTA tile, 8 warps of 32x32, K-chunks of 32,
//      cp.async 3-stage, 1 sync/chunk, 3 CTAs/SM (regs<=85, smem 73KB).
// ---------------------------------------------------------------------------
#define A_TILE_B 8192                    // 128 x 32 bf16
#define B_TILE_B 4096                    // 64 x 32 bf16
#define OFF_AH   0
#define OFF_AL   8192
#define OFF_BH   16384
#define OFF_BL   20480
#define STAGE_B  24576
#define NSTAGE   3
#define SMEM_DYN (NSTAGE * STAGE_B + 1024)

__global__ __launch_bounds__(256, 3)
void gemm_tc(const float* __restrict__ b0, const float* __restrict__ b1,
             const float* __restrict__ b2, float* __restrict__ out_direct, int mode)
{
    extern __shared__ char dsm_raw[];
    char* sm = (char*)(((uintptr_t)dsm_raw + 1023) & ~(uintptr_t)1023);
    const uint32_t sb = smem_u32(sm);
    const int tid = threadIdx.x, wid = tid >> 5, lane = tid & 31;
    const int bn = blockIdx.x * 64, bm = blockIdx.y * 128, z = blockIdx.z;

    const __nv_bfloat16 *Ah, *Al, *Wh, *Wl;
    if (mode == 0) {
        Ah = g_xh; Al = g_xl;
        Wh = g_wh + (size_t)z * D_MODEL * D_MODEL;
        Wl = g_wl + (size_t)z * D_MODEL * D_MODEL;
    } else {
        Ah = g_aoh; Al = g_aol;
        Wh = g_wh + (size_t)3 * D_MODEL * D_MODEL;
        Wl = g_wl + (size_t)3 * D_MODEL * D_MODEL;
    }

    // cp.async mapping.
    // A tiles: row ra = tid/2 (0..127), unit ua = (tid&1)*2 + s, s=0,1
    // B tiles: row rb = tid/4 (0..63),  unit ub = tid&3
    const int ra = tid >> 1;
    const int rb = tid >> 2;
    const __nv_bfloat16* srcAh = Ah + (size_t)(bm + ra) * D_MODEL + (tid & 1) * 16;
    const __nv_bfloat16* srcAl = Al + (size_t)(bm + ra) * D_MODEL + (tid & 1) * 16;
    const __nv_bfloat16* srcBh = Wh + (size_t)(bn + rb) * D_MODEL + (tid & 3) * 8;
    const __nv_bfloat16* srcBl = Wl + (size_t)(bn + rb) * D_MODEL + (tid & 3) * 8;
    uint32_t sts_a[2];
#pragma unroll
    for (int s = 0; s < 2; s++) {
        uint32_t u = (uint32_t)((tid & 1) * 2 + s);
        sts_a[s] = (uint32_t)ra * 64 + ((u ^ ((uint32_t)ra & 3)) << 4);
    }
    const uint32_t sts_b = (uint32_t)rb * 64 +
        (((uint32_t)(tid & 3) ^ ((uint32_t)rb & 3)) << 4);

    // warp tile: 32(M) x 32(N).  4 warps in M, 2 in N.
    const int wm = (wid & 3) * 32;
    const int wn = (wid >> 2) * 32;

    float acc[2][4][4];
#pragma unroll
    for (int mi = 0; mi < 2; mi++)
#pragma unroll
        for (int nj = 0; nj < 4; nj++)
#pragma unroll
            for (int q = 0; q < 4; q++) acc[mi][nj][q] = 0.f;

    const uint32_t lrow = lane & 15;
    const uint32_t lsel = lane >> 4;

    // prologue: chunks 0 and 1 -> stages 0 and 1
#pragma unroll
    for (int pc = 0; pc < 2; pc++) {
        uint32_t stb = sb + (uint32_t)pc * STAGE_B;
#pragma unroll
        for (int s = 0; s < 2; s++) {
            CPA16(stb + OFF_AH + sts_a[s], srcAh + pc * 32 + s * 8);
            CPA16(stb + OFF_AL + sts_a[s], srcAl + pc * 32 + s * 8);
        }
        CPA16(stb + OFF_BH + sts_b, srcBh + pc * 32);
        CPA16(stb + OFF_BL + sts_b, srcBl + pc * 32);
        CPA_COMMIT();
    }

    int stage_c = 0;
    int stage_n = 2;
    for (int c = 0; c < 32; c++) {
        if (c == 31) { CPA_WAIT0(); } else { CPA_WAIT1(); }
        __syncthreads();

        if (c + 2 < 32) {
            uint32_t stb = sb + (uint32_t)stage_n * STAGE_B;
#pragma unroll
            for (int s = 0; s < 2; s++) {
                CPA16(stb + OFF_AH + sts_a[s], srcAh + (c + 2) * 32 + s * 8);
                CPA16(stb + OFF_AL + sts_a[s], srcAl + (c + 2) * 32 + s * 8);
            }
            CPA16(stb + OFF_BH + sts_b, srcBh + (c + 2) * 32);
            CPA16(stb + OFF_BL + sts_b, srcBl + (c + 2) * 32);
            CPA_COMMIT();
        }

        const uint32_t stg = sb + (uint32_t)stage_c * STAGE_B;
#pragma unroll
        for (int kk = 0; kk < 2; kk++) {
            uint32_t bh[2][4], bl[2][4];
#pragma unroll
            for (int jp = 0; jp < 2; jp++) {
                uint32_t rw = (uint32_t)(wn + jp * 16) + lrow;
                uint32_t u  = ((uint32_t)kk * 2 + lsel) ^ (rw & 3);
                uint32_t ab = stg + rw * 64 + (u << 4);
                LDM4(bh[jp], ab + OFF_BH);
                LDM4(bl[jp], ab + OFF_BL);
            }
#pragma unroll
            for (int mi = 0; mi < 2; mi++) {
                uint32_t rr = (uint32_t)(wm + mi * 16) + lrow;
                uint32_t u  = ((uint32_t)kk * 2 + lsel) ^ (rr & 3);
                uint32_t aa = stg + rr * 64 + (u << 4);
                uint32_t ah[4], al[4];
                LDM4(ah, aa + OFF_AH);
                LDM4(al, aa + OFF_AL);
#pragma unroll
                for (int nj = 0; nj < 4; nj++) {
                    const int jp = nj >> 1, w = nj & 1;
                    MMA16816(acc[mi][nj], ah, bh[jp][w], bh[jp][w + 2]);
                }
#pragma unroll
                for (int nj = 0; nj < 4; nj++) {
                    const int jp = nj >> 1, w = nj & 1;
                    MMA16816(acc[mi][nj], ah, bl[jp][w], bl[jp][w + 2]);
                }
#pragma unroll
                for (int nj = 0; nj < 4; nj++) {
                    const int jp = nj >> 1, w = nj & 1;
                    MMA16816(acc[mi][nj], al, bh[jp][w], bh[jp][w + 2]);
                }
            }
        }
        stage_c = (stage_c == NSTAGE - 1) ? 0 : stage_c + 1;
        stage_n = (stage_n == NSTAGE - 1) ? 0 : stage_n + 1;
    }

    // epilogue
    const float* bias;
    float* C;
    if (mode == 0) {
        bias = (z == 0) ? b0 : ((z == 1) ? b1 : b2);
        C = (z == 0) ? g_q : ((z == 1) ? g_k : g_v);
    } else {
        bias = b0;
        C = out_direct;
    }
#pragma unroll
    for (int mi = 0; mi < 2; mi++) {
        const int row = bm + wm + mi * 16 + (lane >> 2);
#pragma unroll
        for (int nj = 0; nj < 4; nj++) {
            const int col = bn + wn + nj * 8 + ((lane & 3) << 1);
            float2 o0 = { acc[mi][nj][0] + bias[col], acc[mi][nj][1] + bias[col + 1] };
            float2 o1 = { acc[mi][nj][2] + bias[col], acc[mi][nj][3] + bias[col + 1] };
            *(float2*)&C[(size_t)row * D_MODEL + col]       = o0;
            *(float2*)&C[(size_t)(row + 8) * D_MODEL + col] = o1;
        }
    }
}

// ---------------------------------------------------------------------------
// Tensor-core flash attention with fused RoPE (unchanged from round 9).
// ---------------------------------------------------------------------------
__device__ __forceinline__ void rope16(float* x1, float* x2, int s, int cb, float scale) {
#pragma unroll
    for (int i = 0; i < 16; i++) {
        float invf = exp2f(-(float)(cb + i) * (13.2877123795494f / 32.f));
        float ang = (float)s * invf;
        float sn, cs;
        sincosf(ang, &sn, &cs);
        float o1 = (x1[i] * cs - x2[i] * sn) * scale;
        float o2 = (x1[i] * sn + x2[i] * cs) * scale;
        x1[i] = o1; x2[i] = o2;
    }
}

__device__ __forceinline__ void store_hl(char* bh, char* bl, int row, int cb, const float* v) {
#pragma unroll
    for (int i = 0; i < 16; i += 2) {
        uint32_t off = (uint32_t)row * 128 + (uint32_t)(cb + i) * 2;
        off ^= ((uint32_t)row & 7) << 4;
        uint32_t oh, ol;
        split2(v[i], v[i + 1], oh, ol);
        *(uint32_t*)(bh + off) = oh;
        *(uint32_t*)(bl + off) = ol;
    }
}

__global__ __launch_bounds__(128)
void attn_tc()
{
    __shared__ __align__(16) char sdata[49152];
    char* sQH = sdata;          char* sQL = sdata + 8192;
    char* sKH = sdata + 16384;  char* sKL = sdata + 24576;
    char* sVH = sdata + 32768;  char* sVL = sdata + 40960;
    const uint32_t sb = smem_u32(sdata);

    const int tid = threadIdx.x, wid = tid >> 5, lane = tid & 31;
    const int q0 = blockIdx.x * 64, h = blockIdx.y, b = blockIdx.z;
    const float* Qg = g_q + (size_t)b * SEQ * D_MODEL + h * DH;
    const float* Kg = g_k + (size_t)b * SEQ * D_MODEL + h * DH;
    const float* Vg = g_v + (size_t)b * SEQ * D_MODEL + h * DH;

    const int lrw = tid >> 1;
    const int lch = (tid & 1) * 16;

    {
        const float* qp = Qg + (size_t)(q0 + lrw) * D_MODEL;
        float x1[16], x2[16];
#pragma unroll
        for (int i = 0; i < 16; i += 4) {
            *(float4*)(x1 + i) = *(const float4*)(qp + lch + i);
            *(float4*)(x2 + i) = *(const float4*)(qp + lch + 32 + i);
        }
        rope16(x1, x2, q0 + lrw, lch, 0.125f);
        store_hl(sQH, sQL, lrw, lch, x1);
        store_hl(sQH, sQL, lrw, lch + 32, x2);
    }

    const int wq = wid * 16;
    float m0 = -1e30f, m1 = -1e30f, l0 = 0.f, l1 = 0.f;
    float acc[8][4];
#pragma unroll
    for (int nb = 0; nb < 8; nb++)
#pragma unroll
        for (int q = 0; q < 4; q++) acc[nb][q] = 0.f;

    int kv0 = q0 - WIN; if (kv0 < 0) kv0 = 0;
    const int nk = q0 + 64 - kv0;

    const int qg0 = q0 + wq + (lane >> 2);
    const int qg1 = qg0 + 8;

    for (int kb = 0; kb < nk; kb += 64) {
        const int kbase = kv0 + kb;

        __syncthreads();
        {
            const float* kp = Kg + (size_t)(kbase + lrw) * D_MODEL;
            float x1[16], x2[16];
#pragma unroll
            for (int i = 0; i < 16; i += 4) {
                *(float4*)(x1 + i) = *(const float4*)(kp + lch + i);
                *(float4*)(x2 + i) = *(const float4*)(kp + lch + 32 + i);
            }
            rope16(x1, x2, kbase + lrw, lch, 1.0f);
            store_hl(sKH, sKL, lrw, lch, x1);
            store_hl(sKH, sKL, lrw, lch + 32, x2);

            const float* vp = Vg + (size_t)(kbase + lrw) * D_MODEL;
            const int vc = (tid & 1) * 32;
            float va[16], vb[16];
#pragma unroll
            for (int i = 0; i < 16; i += 4) {
                *(float4*)(va + i) = *(const float4*)(vp + vc + i);
                *(float4*)(vb + i) = *(const float4*)(vp + vc + 16 + i);
            }
            store_hl(sVH, sVL, lrw, vc, va);
            store_hl(sVH, sVL, lrw, vc + 16, vb);
        }
        __syncthreads();

        float S[8][4];
#pragma unroll
        for (int nb = 0; nb < 8; nb++)
#pragma unroll
            for (int q = 0; q < 4; q++) S[nb][q] = 0.f;

#pragma unroll
        for (int ks = 0; ks < 4; ks++) {
            const uint32_t acb  = (uint32_t)ks * 32 + ((uint32_t)(lane >> 4) << 4);
            const uint32_t arow = (uint32_t)wq + (lane & 15);
            const uint32_t aoff = arow * 128 + (acb ^ ((arow & 7) << 4));
            uint32_t ah[4], al[4];
            LDM4(ah, sb + aoff);
            LDM4(al, sb + 8192 + aoff);
#pragma unroll
            for (int nb2 = 0; nb2 < 4; nb2++) {
                const uint32_t brow = (uint32_t)nb2 * 16 + (lane & 15);
                const uint32_t boff = brow * 128 + (acb ^ ((brow & 7) << 4));
                uint32_t bh[4], bl[4];
                LDM4(bh, sb + 16384 + boff);
                LDM4(bl, sb + 24576 + boff);
#pragma unroll
                for (int w = 0; w < 2; w++) {
                    const int nb = nb2 * 2 + w;
                    MMA16816(S[nb], ah, bh[w], bh[w + 2]);
                    MMA16816(S[nb], ah, bl[w], bl[w + 2]);
                    MMA16816(S[nb], al, bh[w], bh[w + 2]);
                }
            }
        }

#pragma unroll
        for (int nb = 0; nb < 8; nb++) {
            const int kg = kbase + nb * 8 + ((lane & 3) << 1);
            if (kg     > qg0 || kg     < qg0 - WIN) S[nb][0] = -1e30f;
            if (kg + 1 > qg0 || kg + 1 < qg0 - WIN) S[nb][1] = -1e30f;
            if (kg     > qg1 || kg     < qg1 - WIN) S[nb][2] = -1e30f;
            if (kg + 1 > qg1 || kg + 1 < qg1 - WIN) S[nb][3] = -1e30f;
        }
        float mx0 = -1e30f, mx1 = -1e30f;
#pragma unroll
        for (int nb = 0; nb < 8; nb++) {
            mx0 = fmaxf(mx0, fmaxf(S[nb][0], S[nb][1]));
            mx1 = fmaxf(mx1, fmaxf(S[nb][2], S[nb][3]));
        }
        mx0 = fmaxf(mx0, __shfl_xor_sync(0xffffffffu, mx0, 1));
        mx0 = fmaxf(mx0, __shfl_xor_sync(0xffffffffu, mx0, 2));
        mx1 = fmaxf(mx1, __shfl_xor_sync(0xffffffffu, mx1, 1));
        mx1 = fmaxf(mx1, __shfl_xor_sync(0xffffffffu, mx1, 2));

        const float mn0 = fmaxf(m0, mx0), mn1 = fmaxf(m1, mx1);
        const float e0 = __expf(m0 - mn0), e1 = __expf(m1 - mn1);
        m0 = mn0; m1 = mn1;

        float s0 = 0.f, s1 = 0.f;
#pragma unroll
        for (int nb = 0; nb < 8; nb++) {
            S[nb][0] = __expf(S[nb][0] - m0); s0 += S[nb][0];
            S[nb][1] = __expf(S[nb][1] - m0); s0 += S[nb][1];
            S[nb][2] = __expf(S[nb][2] - m1); s1 += S[nb][2];
            S[nb][3] = __expf(S[nb][3] - m1); s1 += S[nb][3];
        }
        s0 += __shfl_xor_sync(0xffffffffu, s0, 1);
        s0 += __shfl_xor_sync(0xffffffffu, s0, 2);
        s1 += __shfl_xor_sync(0xffffffffu, s1, 1);
        s1 += __shfl_xor_sync(0xffffffffu, s1, 2);
        l0 = l0 * e0 + s0;
        l1 = l1 * e1 + s1;
#pragma unroll
        for (int nb = 0; nb < 8; nb++) {
            acc[nb][0] *= e0; acc[nb][1] *= e0;
            acc[nb][2] *= e1; acc[nb][3] *= e1;
        }

#pragma unroll
        for (int j = 0; j < 4; j++) {
            uint32_t pah[4], pal[4];
            split2(S[2 * j][0],     S[2 * j][1],     pah[0], pal[0]);
            split2(S[2 * j][2],     S[2 * j][3],     pah[1], pal[1]);
            split2(S[2 * j + 1][0], S[2 * j + 1][1], pah[2], pal[2]);
            split2(S[2 * j + 1][2], S[2 * j + 1][3], pah[3], pal[3]);

            const uint32_t vrow = (uint32_t)j * 16 + (lane & 15);
#pragma unroll
            for (int nb2 = 0; nb2 < 4; nb2++) {
                const uint32_t vcb = (uint32_t)nb2 * 32 + ((uint32_t)(lane >> 4) << 4);
                const uint32_t boff = vrow * 128 + (vcb ^ ((vrow & 7) << 4));
                uint32_t vh[4], vl[4];
                LDM4T(vh, sb + 32768 + boff);
                LDM4T(vl, sb + 40960 + boff);
#pragma unroll
                for (int w = 0; w < 2; w++) {
                    const int nb = nb2 * 2 + w;
                    MMA16816(acc[nb], pah, vh[2 * w], vh[2 * w + 1]);
                    MMA16816(acc[nb], pal, vh[2 * w], vh[2 * w + 1]);
                    MMA16816(acc[nb], pah, vl[2 * w], vl[2 * w + 1]);
                }
            }
        }
    }

    const float inv0 = 1.f / l0, inv1 = 1.f / l1;
#pragma unroll
    for (int nb = 0; nb < 8; nb++) {
        const int col = h * DH + nb * 8 + ((lane & 3) << 1);
        const size_t i0 = ((size_t)b * SEQ + qg0) * D_MODEL + col;
        const size_t i1 = ((size_t)b * SEQ + qg1) * D_MODEL + col;
        uint32_t oh, ol;
        split2(acc[nb][0] * inv0, acc[nb][1] * inv0, oh, ol);
        *(uint32_t*)(g_aoh + i0) = oh;
        *(uint32_t*)(g_aol + i0) = ol;
        split2(acc[nb][2] * inv1, acc[nb][3] * inv1, oh, ol);
        *(uint32_t*)(g_aoh + i1) = oh;
        *(uint32_t*)(g_aol + i1) = ol;
    }
}

// ---------------------------------------------------------------------------
extern "C" void kernel_launch(void* const* d_in, const int* in_sizes, int n_in,
                              void* d_out, int out_size)
{
    const float* x  = (const float*)d_in[0];
    const float* Wq = (const float*)d_in[1];
    const float* bq = (const float*)d_in[2];
    const float* Wk = (const float*)d_in[3];
    const float* bk = (const float*)d_in[4];
    const float* Wv = (const float*)d_in[5];
    const float* bv = (const float*)d_in[6];
    const float* Wo = (const float*)d_in[7];
    const float* bo = (const float*)d_in[8];
    float* out = (float*)d_out;

    cudaFuncSetAttribute(gemm_tc, cudaFuncAttributeMaxDynamicSharedMemorySize, SMEM_DYN);

    conv_all<<<8192, 256>>>(x, Wq, Wk, Wv, Wo);

    gemm_tc<<<dim3(16, 32, 3), 256, SMEM_DYN>>>(bq, bk, bv, nullptr, 0);

    dim3 agrid(SEQ / 64, NHEADS, BATCH);
    attn_tc<<<agrid, 128>>>();

    gemm_tc<<<dim3(16, 32, 1), 256, SMEM_DYN>>>(bo, nullptr, nullptr, out, 1);
}

// round 11
// speedup vs baseline: 1.0393x; 1.0393x over previous
#include <cuda_runtime.h>
#include <cuda_bf16.h>
#include <math.h>
#include <stdint.h>

#define D_MODEL 1024
#define NHEADS  16
#define DH      64
#define SEQ     2048
#define BATCH   2
#define WIN     128
#define MROWS   (BATCH * SEQ)   // 4096

// ---------------- scratch (static device memory) ----------------
__device__ float g_q [MROWS * D_MODEL];
__device__ float g_k [MROWS * D_MODEL];
__device__ float g_v [MROWS * D_MODEL];

__device__ float g_xt [MROWS * D_MODEL];          // x, tf32-rounded, K-permuted
__device__ float g_wt [3 * D_MODEL * D_MODEL];    // Wq/Wk/Wv, tf32, K-permuted
__device__ __nv_bfloat16 g_woh[D_MODEL * D_MODEL];
__device__ __nv_bfloat16 g_wol[D_MODEL * D_MODEL];
__device__ __nv_bfloat16 g_aoh[MROWS * D_MODEL];
__device__ __nv_bfloat16 g_aol[MROWS * D_MODEL];

// ---------------- PTX helpers ----------------
__device__ __forceinline__ uint32_t smem_u32(const void* p) {
    uint32_t a;
    asm("{ .reg .u64 t; cvta.to.shared.u64 t, %1; cvt.u32.u64 %0, t; }"
        : "=r"(a) : "l"(p));
    return a;
}
#define CPA16(dst, src) \
    asm volatile("cp.async.cg.shared.global [%0], [%1], 16;" :: "r"(dst), "l"(src))
#define CPA_COMMIT() asm volatile("cp.async.commit_group;" ::: "memory")
#define CPA_WAIT1()  asm volatile("cp.async.wait_group 1;" ::: "memory")
#define CPA_WAIT0()  asm volatile("cp.async.wait_group 0;" ::: "memory")

#define LDM4(r, addr) \
    asm volatile("ldmatrix.sync.aligned.m8n8.x4.shared.b16 {%0,%1,%2,%3}, [%4];" \
        : "=r"((r)[0]), "=r"((r)[1]), "=r"((r)[2]), "=r"((r)[3]) : "r"(addr))

#define LDM4T(r, addr) \
    asm volatile("ldmatrix.sync.aligned.m8n8.x4.trans.shared.b16 {%0,%1,%2,%3}, [%4];" \
        : "=r"((r)[0]), "=r"((r)[1]), "=r"((r)[2]), "=r"((r)[3]) : "r"(addr))

#define MMA16816(acc, a, b0, b1) \
    asm volatile("mma.sync.aligned.m16n8k16.row.col.f32.bf16.bf16.f32 " \
        "{%0,%1,%2,%3}, {%4,%5,%6,%7}, {%8,%9}, {%0,%1,%2,%3};" \
        : "+f"((acc)[0]), "+f"((acc)[1]), "+f"((acc)[2]), "+f"((acc)[3]) \
        : "r"((a)[0]), "r"((a)[1]), "r"((a)[2]), "r"((a)[3]), "r"(b0), "r"(b1))

#define MMAT32(acc, a0, a1, a2, a3, b0, b1) \
    asm volatile("mma.sync.aligned.m16n8k8.row.col.f32.tf32.tf32.f32 " \
        "{%0,%1,%2,%3}, {%4,%5,%6,%7}, {%8,%9}, {%0,%1,%2,%3};" \
        : "+f"((acc)[0]), "+f"((acc)[1]), "+f"((acc)[2]), "+f"((acc)[3]) \
        : "r"(a0), "r"(a1), "r"(a2), "r"(a3), "r"(b0), "r"(b1))

#define LDSV2(r0, r1, addr) \
    asm volatile("ld.shared.v2.b32 {%0,%1}, [%2];" : "=r"(r0), "=r"(r1) : "r"(addr))

__device__ __forceinline__ uint32_t to_tf32(float f) {
    uint32_t o;
    asm("cvt.rna.tf32.f32 %0, %1;" : "=r"(o) : "f"(f));
    return o;
}

__device__ __forceinline__ void split2(float x, float y, uint32_t& oh, uint32_t& ol) {
    __nv_bfloat16 hx = __float2bfloat16(x), hy = __float2bfloat16(y);
    __nv_bfloat162 th; th.x = hx; th.y = hy;
    __nv_bfloat162 tl;
    tl.x = __float2bfloat16(x - __bfloat162float(hx));
    tl.y = __float2bfloat16(y - __bfloat162float(hy));
    oh = *(uint32_t*)&th; ol = *(uint32_t*)&tl;
}

// ---------------------------------------------------------------------------
// Conversions, one launch.
// blocks [0,2048):        x -> g_xt   (tf32, K-permuted; 8 floats/thread)
// blocks [2048,3584):     Wq/Wk/Wv -> g_wt (tf32, K-permuted)
// blocks [3584,4608):     Wo -> g_woh/g_wol (bf16 hi/lo; 4 floats/thread)
// K-permutation per 8-group: dst = [s0,s4,s1,s5,s2,s6,s3,s7].
// ---------------------------------------------------------------------------
__global__ __launch_bounds__(256)
void conv_all(const float* __restrict__ x,
              const float* __restrict__ Wq, const float* __restrict__ Wk,
              const float* __restrict__ Wv, const float* __restrict__ Wo)
{
    int blk = blockIdx.x;
    if (blk < 3584) {
        const float* src;
        float* dst;
        int i;
        if (blk < 2048) {
            src = x; dst = g_xt; i = blk * 256 + threadIdx.x;
        } else {
            int w  = (blk - 2048) >> 9;          // 512 blocks each
            int bb = (blk - 2048) & 511;
            src = (w == 0) ? Wq : (w == 1) ? Wk : Wv;
            dst = g_wt + (size_t)w * D_MODEL * D_MODEL;
            i = bb * 256 + threadIdx.x;
        }
        float4 f0 = ((const float4*)src)[i * 2];
        float4 f1 = ((const float4*)src)[i * 2 + 1];
        uint32_t t0 = to_tf32(f0.x), t1 = to_tf32(f0.y);
        uint32_t t2 = to_tf32(f0.z), t3 = to_tf32(f0.w);
        uint32_t t4 = to_tf32(f1.x), t5 = to_tf32(f1.y);
        uint32_t t6 = to_tf32(f1.z), t7 = to_tf32(f1.w);
        uint4 d0 = { t0, t4, t1, t5 };
        uint4 d1 = { t2, t6, t3, t7 };
        ((uint4*)dst)[i * 2]     = d0;
        ((uint4*)dst)[i * 2 + 1] = d1;
    } else {
        int i = (blk - 3584) * 256 + threadIdx.x;
        float4 v = ((const float4*)Wo)[i];
        uint32_t h01, l01, h23, l23;
        split2(v.x, v.y, h01, l01);
        split2(v.z, v.w, h23, l23);
        ((uint32_t*)g_woh)[i * 2]     = h01;
        ((uint32_t*)g_woh)[i * 2 + 1] = h23;
        ((uint32_t*)g_wol)[i * 2]     = l01;
        ((uint32_t*)g_wol)[i * 2 + 1] = l23;
    }
}

// ---------------------------------------------------------------------------
// TF32 single-pass QKV GEMM: C[z] = x*W[z]^T + bias[z].
// 128x128 CTA tile, 8 warps (64x32), K-chunks of 32 (4 k8 steps),
// cp.async 3-stage, 1 sync/chunk, 2 CTAs/SM.  Operands tf32, K-permuted.
// smem rows padded to 144B -> conflict-minimal v2 fragment loads.
// ---------------------------------------------------------------------------
#define T32_ROWB   144
#define T32_TILE   18432            // 128 * 144
#define T32_STAGE  36864
#define T32_NSTAGE 3
#define SMEM_T32   (T32_NSTAGE * T32_STAGE + 1024)

__global__ __launch_bounds__(256, 2)
void gemm_tf32(const float* __restrict__ b0, const float* __restrict__ b1,
               const float* __restrict__ b2)
{
    extern __shared__ char dsm_raw[];
    char* sm = (char*)(((uintptr_t)dsm_raw + 1023) & ~(uintptr_t)1023);
    const uint32_t sb = smem_u32(sm);
    const int tid = threadIdx.x, wid = tid >> 5, lane = tid & 31;
    const int bn = blockIdx.x * 128, bm = blockIdx.y * 128, z = blockIdx.z;

    const float* A = g_xt;
    const float* W = g_wt + (size_t)z * D_MODEL * D_MODEL;
    const float* bias = (z == 0) ? b0 : ((z == 1) ? b1 : b2);
    float* C = (z == 0) ? g_q : ((z == 1) ? g_k : g_v);

    // cp.async mapping: row = tid/2, half = tid&1 owns 16 floats (4 segs of 16B)
    const int row = tid >> 1;
    const int half = tid & 1;
    const float* srcA = A + (size_t)(bm + row) * D_MODEL + half * 16;
    const float* srcW = W + (size_t)(bn + row) * D_MODEL + half * 16;
    const uint32_t dstb = (uint32_t)row * T32_ROWB + (uint32_t)half * 64;

    const int wm = (wid & 1) * 64;
    const int wn = (wid >> 1) * 32;
    const uint32_t r4 = lane >> 2;      // 0..7
    const uint32_t c4 = lane & 3;       // 0..3

    float acc[4][4][4];
#pragma unroll
    for (int mi = 0; mi < 4; mi++)
#pragma unroll
        for (int nj = 0; nj < 4; nj++)
#pragma unroll
            for (int q = 0; q < 4; q++) acc[mi][nj][q] = 0.f;

    // prologue: chunks 0 and 1
#pragma unroll
    for (int pc = 0; pc < 2; pc++) {
        uint32_t stb = sb + (uint32_t)pc * T32_STAGE;
#pragma unroll
        for (int s = 0; s < 4; s++) {
            CPA16(stb + dstb + s * 16, srcA + pc * 32 + s * 4);
            CPA16(stb + T32_TILE + dstb + s * 16, srcW + pc * 32 + s * 4);
        }
        CPA_COMMIT();
    }

    int stage_c = 0;
    int stage_n = 2;
    for (int c = 0; c < 32; c++) {
        if (c == 31) { CPA_WAIT0(); } else { CPA_WAIT1(); }
        __syncthreads();

        if (c + 2 < 32) {
            uint32_t stb = sb + (uint32_t)stage_n * T32_STAGE;
#pragma unroll
            for (int s = 0; s < 4; s++) {
                CPA16(stb + dstb + s * 16, srcA + (c + 2) * 32 + s * 4);
                CPA16(stb + T32_TILE + dstb + s * 16, srcW + (c + 2) * 32 + s * 4);
            }
            CPA_COMMIT();
        }

        const uint32_t stg = sb + (uint32_t)stage_c * T32_STAGE;
#pragma unroll
        for (int kk = 0; kk < 4; kk++) {
            const uint32_t coff = (uint32_t)kk * 32 + c4 * 8;
            // B fragments: 4 n8 groups
            uint32_t bb0[4], bb1[4];
#pragma unroll
            for (int jp = 0; jp < 4; jp++) {
                uint32_t ba = stg + T32_TILE +
                    ((uint32_t)(wn + jp * 8) + r4) * T32_ROWB + coff;
                LDSV2(bb0[jp], bb1[jp], ba);
            }
#pragma unroll
            for (int mi = 0; mi < 4; mi++) {
                uint32_t aa = stg + ((uint32_t)(wm + mi * 16) + r4) * T32_ROWB + coff;
                uint32_t a0, a2, a1, a3;
                LDSV2(a0, a2, aa);
                LDSV2(a1, a3, aa + 8 * T32_ROWB);
#pragma unroll
                for (int nj = 0; nj < 4; nj++)
                    MMAT32(acc[mi][nj], a0, a1, a2, a3, bb0[nj], bb1[nj]);
            }
        }
        stage_c = (stage_c == T32_NSTAGE - 1) ? 0 : stage_c + 1;
        stage_n = (stage_n == T32_NSTAGE - 1) ? 0 : stage_n + 1;
    }

#pragma unroll
    for (int mi = 0; mi < 4; mi++) {
        const int orow = bm + wm + mi * 16 + (lane >> 2);
#pragma unroll
        for (int nj = 0; nj < 4; nj++) {
            const int col = bn + wn + nj * 8 + ((lane & 3) << 1);
            float2 o0 = { acc[mi][nj][0] + bias[col], acc[mi][nj][1] + bias[col + 1] };
            float2 o1 = { acc[mi][nj][2] + bias[col], acc[mi][nj][3] + bias[col + 1] };
            *(float2*)&C[(size_t)orow * D_MODEL + col]       = o0;
            *(float2*)&C[(size_t)(orow + 8) * D_MODEL + col] = o1;
        }
    }
}

// ---------------------------------------------------------------------------
// O-projection: bf16-split GEMM (R7-proven pipeline).  out = ao*Wo^T + bo.
// ---------------------------------------------------------------------------
#define TILE_B  8192
#define STAGE_B 32768
#define NSTAGE  3
#define SMEM_O  (NSTAGE * STAGE_B + 1024)

__global__ __launch_bounds__(256, 2)
void gemm_o(const float* __restrict__ bo, float* __restrict__ out)
{
    extern __shared__ char dsm_raw[];
    char* sm = (char*)(((uintptr_t)dsm_raw + 1023) & ~(uintptr_t)1023);
    const uint32_t sb = smem_u32(sm);
    const int tid = threadIdx.x, wid = tid >> 5, lane = tid & 31;
    const int bn = blockIdx.x * 128, bm = blockIdx.y * 128;

    const int r = tid >> 1;
    const int half = tid & 1;
    const __nv_bfloat16* srcs[4] = {
        g_aoh + (size_t)(bm + r) * D_MODEL + half * 16,
        g_aol + (size_t)(bm + r) * D_MODEL + half * 16,
        g_woh + (size_t)(bn + r) * D_MODEL + half * 16,
        g_wol + (size_t)(bn + r) * D_MODEL + half * 16 };
    uint32_t sts_off[2];
#pragma unroll
    for (int s = 0; s < 2; s++) {
        uint32_t u = (uint32_t)(half * 2 + s);
        sts_off[s] = (uint32_t)r * 64 + ((u ^ ((uint32_t)r & 3)) << 4);
    }

    const int wm = (wid & 1) * 64;
    const int wn = (wid >> 1) * 32;

    float acc[4][4][4];
#pragma unroll
    for (int mi = 0; mi < 4; mi++)
#pragma unroll
        for (int nj = 0; nj < 4; nj++)
#pragma unroll
            for (int q = 0; q < 4; q++) acc[mi][nj][q] = 0.f;

    const uint32_t lrow = lane & 15;
    const uint32_t lsel = lane >> 4;

#pragma unroll
    for (int pc = 0; pc < 2; pc++) {
        uint32_t stb = sb + (uint32_t)pc * STAGE_B;
#pragma unroll
        for (int t = 0; t < 4; t++)
#pragma unroll
            for (int s = 0; s < 2; s++)
                CPA16(stb + t * TILE_B + sts_off[s], srcs[t] + pc * 32 + s * 8);
        CPA_COMMIT();
    }

    int stage_c = 0;
    int stage_n = 2;
    for (int c = 0; c < 32; c++) {
        if (c == 31) { CPA_WAIT0(); } else { CPA_WAIT1(); }
        __syncthreads();

        if (c + 2 < 32) {
            uint32_t stb = sb + (uint32_t)stage_n * STAGE_B;
#pragma unroll
            for (int t = 0; t < 4; t++)
#pragma unroll
                for (int s = 0; s < 2; s++)
                    CPA16(stb + t * TILE_B + sts_off[s], srcs[t] + (c + 2) * 32 + s * 8);
            CPA_COMMIT();
        }

        const uint32_t stg = sb + (uint32_t)stage_c * STAGE_B;
#pragma unroll
        for (int kk = 0; kk < 2; kk++) {
            uint32_t bh[2][4], bl[2][4];
#pragma unroll
            for (int jp = 0; jp < 2; jp++) {
                uint32_t rw = (uint32_t)(wn + jp * 16) + lrow;
                uint32_t u  = ((uint32_t)kk * 2 + lsel) ^ (rw & 3);
                uint32_t ab = stg + rw * 64 + (u << 4);
                LDM4(bh[jp], ab + 2 * TILE_B);
                LDM4(bl[jp], ab + 3 * TILE_B);
            }
#pragma unroll
            for (int mi = 0; mi < 4; mi++) {
                uint32_t ra = (uint32_t)(wm + mi * 16) + lrow;
                uint32_t u  = ((uint32_t)kk * 2 + lsel) ^ (ra & 3);
                uint32_t aa = stg + ra * 64 + (u << 4);
                uint32_t ah[4], al[4];
                LDM4(ah, aa);
                LDM4(al, aa + TILE_B);
#pragma unroll
                for (int nj = 0; nj < 4; nj++) {
                    const int jp = nj >> 1, w = nj & 1;
                    MMA16816(acc[mi][nj], ah, bh[jp][w], bh[jp][w + 2]);
                    MMA16816(acc[mi][nj], ah, bl[jp][w], bl[jp][w + 2]);
                    MMA16816(acc[mi][nj], al, bh[jp][w], bh[jp][w + 2]);
                }
            }
        }
        stage_c = (stage_c == NSTAGE - 1) ? 0 : stage_c + 1;
        stage_n = (stage_n == NSTAGE - 1) ? 0 : stage_n + 1;
    }

#pragma unroll
    for (int mi = 0; mi < 4; mi++) {
        const int orow = bm + wm + mi * 16 + (lane >> 2);
#pragma unroll
        for (int nj = 0; nj < 4; nj++) {
            const int col = bn + wn + nj * 8 + ((lane & 3) << 1);
            float2 o0 = { acc[mi][nj][0] + bo[col], acc[mi][nj][1] + bo[col + 1] };
            float2 o1 = { acc[mi][nj][2] + bo[col], acc[mi][nj][3] + bo[col + 1] };
            *(float2*)&out[(size_t)orow * D_MODEL + col]       = o0;
            *(float2*)&out[(size_t)(orow + 8) * D_MODEL + col] = o1;
        }
    }
}

// ---------------------------------------------------------------------------
// Tensor-core flash attention with fused RoPE (unchanged from round 9).
// ---------------------------------------------------------------------------
__device__ __forceinline__ void rope16(float* x1, float* x2, int s, int cb, float scale) {
#pragma unroll
    for (int i = 0; i < 16; i++) {
        float invf = exp2f(-(float)(cb + i) * (13.2877123795494f / 32.f));
        float ang = (float)s * invf;
        float sn, cs;
        sincosf(ang, &sn, &cs);
        float o1 = (x1[i] * cs - x2[i] * sn) * scale;
        float o2 = (x1[i] * sn + x2[i] * cs) * scale;
        x1[i] = o1; x2[i] = o2;
    }
}

__device__ __forceinline__ void store_hl(char* bh, char* bl, int row, int cb, const float* v) {
#pragma unroll
    for (int i = 0; i < 16; i += 2) {
        uint32_t off = (uint32_t)row * 128 + (uint32_t)(cb + i) * 2;
        off ^= ((uint32_t)row & 7) << 4;
        uint32_t oh, ol;
        split2(v[i], v[i + 1], oh, ol);
        *(uint32_t*)(bh + off) = oh;
        *(uint32_t*)(bl + off) = ol;
    }
}

__global__ __launch_bounds__(128)
void attn_tc()
{
    __shared__ __align__(16) char sdata[49152];
    char* sQH = sdata;          char* sQL = sdata + 8192;
    char* sKH = sdata + 16384;  char* sKL = sdata + 24576;
    char* sVH = sdata + 32768;  char* sVL = sdata + 40960;
    const uint32_t sb = smem_u32(sdata);

    const int tid = threadIdx.x, wid = tid >> 5, lane = tid & 31;
    const int q0 = blockIdx.x * 64, h = blockIdx.y, b = blockIdx.z;
    const float* Qg = g_q + (size_t)b * SEQ * D_MODEL + h * DH;
    const float* Kg = g_k + (size_t)b * SEQ * D_MODEL + h * DH;
    const float* Vg = g_v + (size_t)b * SEQ * D_MODEL + h * DH;

    const int lrw = tid >> 1;
    const int lch = (tid & 1) * 16;

    {
        const float* qp = Qg + (size_t)(q0 + lrw) * D_MODEL;
        float x1[16], x2[16];
#pragma unroll
        for (int i = 0; i < 16; i += 4) {
            *(float4*)(x1 + i) = *(const float4*)(qp + lch + i);
            *(float4*)(x2 + i) = *(const float4*)(qp + lch + 32 + i);
        }
        rope16(x1, x2, q0 + lrw, lch, 0.125f);
        store_hl(sQH, sQL, lrw, lch, x1);
        store_hl(sQH, sQL, lrw, lch + 32, x2);
    }

    const int wq = wid * 16;
    float m0 = -1e30f, m1 = -1e30f, l0 = 0.f, l1 = 0.f;
    float acc[8][4];
#pragma unroll
    for (int nb = 0; nb < 8; nb++)
#pragma unroll
        for (int q = 0; q < 4; q++) acc[nb][q] = 0.f;

    int kv0 = q0 - WIN; if (kv0 < 0) kv0 = 0;
    const int nk = q0 + 64 - kv0;

    const int qg0 = q0 + wq + (lane >> 2);
    const int qg1 = qg0 + 8;

    for (int kb = 0; kb < nk; kb += 64) {
        const int kbase = kv0 + kb;

        __syncthreads();
        {
            const float* kp = Kg + (size_t)(kbase + lrw) * D_MODEL;
            float x1[16], x2[16];
#pragma unroll
            for (int i = 0; i < 16; i += 4) {
                *(float4*)(x1 + i) = *(const float4*)(kp + lch + i);
                *(float4*)(x2 + i) = *(const float4*)(kp + lch + 32 + i);
            }
            rope16(x1, x2, kbase + lrw, lch, 1.0f);
            store_hl(sKH, sKL, lrw, lch, x1);
            store_hl(sKH, sKL, lrw, lch + 32, x2);

            const float* vp = Vg + (size_t)(kbase + lrw) * D_MODEL;
            const int vc = (tid & 1) * 32;
            float va[16], vb[16];
#pragma unroll
            for (int i = 0; i < 16; i += 4) {
                *(float4*)(va + i) = *(const float4*)(vp + vc + i);
                *(float4*)(vb + i) = *(const float4*)(vp + vc + 16 + i);
            }
            store_hl(sVH, sVL, lrw, vc, va);
            store_hl(sVH, sVL, lrw, vc + 16, vb);
        }
        __syncthreads();

        float S[8][4];
#pragma unroll
        for (int nb = 0; nb < 8; nb++)
#pragma unroll
            for (int q = 0; q < 4; q++) S[nb][q] = 0.f;

#pragma unroll
        for (int ks = 0; ks < 4; ks++) {
            const uint32_t acb  = (uint32_t)ks * 32 + ((uint32_t)(lane >> 4) << 4);
            const uint32_t arow = (uint32_t)wq + (lane & 15);
            const uint32_t aoff = arow * 128 + (acb ^ ((arow & 7) << 4));
            uint32_t ah[4], al[4];
            LDM4(ah, sb + aoff);
            LDM4(al, sb + 8192 + aoff);
#pragma unroll
            for (int nb2 = 0; nb2 < 4; nb2++) {
                const uint32_t brow = (uint32_t)nb2 * 16 + (lane & 15);
                const uint32_t boff = brow * 128 + (acb ^ ((brow & 7) << 4));
                uint32_t bh[4], bl[4];
                LDM4(bh, sb + 16384 + boff);
                LDM4(bl, sb + 24576 + boff);
#pragma unroll
                for (int w = 0; w < 2; w++) {
                    const int nb = nb2 * 2 + w;
                    MMA16816(S[nb], ah, bh[w], bh[w + 2]);
                    MMA16816(S[nb], ah, bl[w], bl[w + 2]);
                    MMA16816(S[nb], al, bh[w], bh[w + 2]);
                }
            }
        }

#pragma unroll
        for (int nb = 0; nb < 8; nb++) {
            const int kg = kbase + nb * 8 + ((lane & 3) << 1);
            if (kg     > qg0 || kg     < qg0 - WIN) S[nb][0] = -1e30f;
            if (kg + 1 > qg0 || kg + 1 < qg0 - WIN) S[nb][1] = -1e30f;
            if (kg     > qg1 || kg     < qg1 - WIN) S[nb][2] = -1e30f;
            if (kg + 1 > qg1 || kg + 1 < qg1 - WIN) S[nb][3] = -1e30f;
        }
        float mx0 = -1e30f, mx1 = -1e30f;
#pragma unroll
        for (int nb = 0; nb < 8; nb++) {
            mx0 = fmaxf(mx0, fmaxf(S[nb][0], S[nb][1]));
            mx1 = fmaxf(mx1, fmaxf(S[nb][2], S[nb][3]));
        }
        mx0 = fmaxf(mx0, __shfl_xor_sync(0xffffffffu, mx0, 1));
        mx0 = fmaxf(mx0, __shfl_xor_sync(0xffffffffu, mx0, 2));
        mx1 = fmaxf(mx1, __shfl_xor_sync(0xffffffffu, mx1, 1));
        mx1 = fmaxf(mx1, __shfl_xor_sync(0xffffffffu, mx1, 2));

        const float mn0 = fmaxf(m0, mx0), mn1 = fmaxf(m1, mx1);
        const float e0 = __expf(m0 - mn0), e1 = __expf(m1 - mn1);
        m0 = mn0; m1 = mn1;

        float s0 = 0.f, s1 = 0.f;
#pragma unroll
        for (int nb = 0; nb < 8; nb++) {
            S[nb][0] = __expf(S[nb][0] - m0); s0 += S[nb][0];
            S[nb][1] = __expf(S[nb][1] - m0); s0 += S[nb][1];
            S[nb][2] = __expf(S[nb][2] - m1); s1 += S[nb][2];
            S[nb][3] = __expf(S[nb][3] - m1); s1 += S[nb][3];
        }
        s0 += __shfl_xor_sync(0xffffffffu, s0, 1);
        s0 += __shfl_xor_sync(0xffffffffu, s0, 2);
        s1 += __shfl_xor_sync(0xffffffffu, s1, 1);
        s1 += __shfl_xor_sync(0xffffffffu, s1, 2);
        l0 = l0 * e0 + s0;
        l1 = l1 * e1 + s1;
#pragma unroll
        for (int nb = 0; nb < 8; nb++) {
            acc[nb][0] *= e0; acc[nb][1] *= e0;
            acc[nb][2] *= e1; acc[nb][3] *= e1;
        }

#pragma unroll
        for (int j = 0; j < 4; j++) {
            uint32_t pah[4], pal[4];
            split2(S[2 * j][0],     S[2 * j][1],     pah[0], pal[0]);
            split2(S[2 * j][2],     S[2 * j][3],     pah[1], pal[1]);
            split2(S[2 * j + 1][0], S[2 * j + 1][1], pah[2], pal[2]);
            split2(S[2 * j + 1][2], S[2 * j + 1][3], pah[3], pal[3]);

            const uint32_t vrow = (uint32_t)j * 16 + (lane & 15);
#pragma unroll
            for (int nb2 = 0; nb2 < 4; nb2++) {
                const uint32_t vcb = (uint32_t)nb2 * 32 + ((uint32_t)(lane >> 4) << 4);
                const uint32_t boff = vrow * 128 + (vcb ^ ((vrow & 7) << 4));
                uint32_t vh[4], vl[4];
                LDM4T(vh, sb + 32768 + boff);
                LDM4T(vl, sb + 40960 + boff);
#pragma unroll
                for (int w = 0; w < 2; w++) {
                    const int nb = nb2 * 2 + w;
                    MMA16816(acc[nb], pah, vh[2 * w], vh[2 * w + 1]);
                    MMA16816(acc[nb], pal, vh[2 * w], vh[2 * w + 1]);
                    MMA16816(acc[nb], pah, vl[2 * w], vl[2 * w + 1]);
                }
            }
        }
    }

    const float inv0 = 1.f / l0, inv1 = 1.f / l1;
#pragma unroll
    for (int nb = 0; nb < 8; nb++) {
        const int col = h * DH + nb * 8 + ((lane & 3) << 1);
        const size_t i0 = ((size_t)b * SEQ + qg0) * D_MODEL + col;
        const size_t i1 = ((size_t)b * SEQ + qg1) * D_MODEL + col;
        uint32_t oh, ol;
        split2(acc[nb][0] * inv0, acc[nb][1] * inv0, oh, ol);
        *(uint32_t*)(g_aoh + i0) = oh;
        *(uint32_t*)(g_aol + i0) = ol;
        split2(acc[nb][2] * inv1, acc[nb][3] * inv1, oh, ol);
        *(uint32_t*)(g_aoh + i1) = oh;
        *(uint32_t*)(g_aol + i1) = ol;
    }
}

// ---------------------------------------------------------------------------
extern "C" void kernel_launch(void* const* d_in, const int* in_sizes, int n_in,
                              void* d_out, int out_size)
{
    const float* x  = (const float*)d_in[0];
    const float* Wq = (const float*)d_in[1];
    const float* bq = (const float*)d_in[2];
    const float* Wk = (const float*)d_in[3];
    const float* bk = (const float*)d_in[4];
    const float* Wv = (const float*)d_in[5];
    const float* bv = (const float*)d_in[6];
    const float* Wo = (const float*)d_in[7];
    const float* bo = (const float*)d_in[8];
    float* out = (float*)d_out;

    cudaFuncSetAttribute(gemm_tf32, cudaFuncAttributeMaxDynamicSharedMemorySize, SMEM_T32);
    cudaFuncSetAttribute(gemm_o,    cudaFuncAttributeMaxDynamicSharedMemorySize, SMEM_O);

    conv_all<<<4608, 256>>>(x, Wq, Wk, Wv, Wo);

    gemm_tf32<<<dim3(8, 32, 3), 256, SMEM_T32>>>(bq, bk, bv);

    dim3 agrid(SEQ / 64, NHEADS, BATCH);
    attn_tc<<<agrid, 128>>>();

    gemm_o<<<dim3(8, 32), 256, SMEM_O>>>(bo, out);
}

// round 12
// speedup vs baseline: 1.9331x; 1.8601x over previous
#include <cuda_runtime.h>
#include <cuda_bf16.h>
#include <cuda_fp16.h>
#include <math.h>
#include <stdint.h>

#define D_MODEL 1024
#define NHEADS  16
#define DH      64
#define SEQ     2048
#define BATCH   2
#define WIN     128
#define MROWS   (BATCH * SEQ)   // 4096

// ---------------- scratch (static device memory) ----------------
__device__ float g_q [MROWS * D_MODEL];
__device__ float g_k [MROWS * D_MODEL];
__device__ float g_v [MROWS * D_MODEL];

__device__ __half g_xf [MROWS * D_MODEL];          // x,  fp16
__device__ __half g_wf [3 * D_MODEL * D_MODEL];    // Wq/Wk/Wv, fp16
__device__ __half g_wof[D_MODEL * D_MODEL];        // Wo, fp16
__device__ __half g_aof[MROWS * D_MODEL];          // attn out, fp16

// ---------------- PTX helpers ----------------
__device__ __forceinline__ uint32_t smem_u32(const void* p) {
    uint32_t a;
    asm("{ .reg .u64 t; cvta.to.shared.u64 t, %1; cvt.u32.u64 %0, t; }"
        : "=r"(a) : "l"(p));
    return a;
}
#define CPA16(dst, src) \
    asm volatile("cp.async.cg.shared.global [%0], [%1], 16;" :: "r"(dst), "l"(src))
#define CPA_COMMIT() asm volatile("cp.async.commit_group;" ::: "memory")
#define CPA_WAIT1()  asm volatile("cp.async.wait_group 1;" ::: "memory")
#define CPA_WAIT0()  asm volatile("cp.async.wait_group 0;" ::: "memory")

#define LDM4(r, addr) \
    asm volatile("ldmatrix.sync.aligned.m8n8.x4.shared.b16 {%0,%1,%2,%3}, [%4];" \
        : "=r"((r)[0]), "=r"((r)[1]), "=r"((r)[2]), "=r"((r)[3]) : "r"(addr))

#define LDM4T(r, addr) \
    asm volatile("ldmatrix.sync.aligned.m8n8.x4.trans.shared.b16 {%0,%1,%2,%3}, [%4];" \
        : "=r"((r)[0]), "=r"((r)[1]), "=r"((r)[2]), "=r"((r)[3]) : "r"(addr))

// bf16 mma (used by attention)
#define MMA16816(acc, a, b0, b1) \
    asm volatile("mma.sync.aligned.m16n8k16.row.col.f32.bf16.bf16.f32 " \
        "{%0,%1,%2,%3}, {%4,%5,%6,%7}, {%8,%9}, {%0,%1,%2,%3};" \
        : "+f"((acc)[0]), "+f"((acc)[1]), "+f"((acc)[2]), "+f"((acc)[3]) \
        : "r"((a)[0]), "r"((a)[1]), "r"((a)[2]), "r"((a)[3]), "r"(b0), "r"(b1))

// fp16 mma (single-pass GEMMs)
#define MMAF16(acc, a, b0, b1) \
    asm volatile("mma.sync.aligned.m16n8k16.row.col.f32.f16.f16.f32 " \
        "{%0,%1,%2,%3}, {%4,%5,%6,%7}, {%8,%9}, {%0,%1,%2,%3};" \
        : "+f"((acc)[0]), "+f"((acc)[1]), "+f"((acc)[2]), "+f"((acc)[3]) \
        : "r"((a)[0]), "r"((a)[1]), "r"((a)[2]), "r"((a)[3]), "r"(b0), "r"(b1))

__device__ __forceinline__ void split2(float x, float y, uint32_t& oh, uint32_t& ol) {
    __nv_bfloat16 hx = __float2bfloat16(x), hy = __float2bfloat16(y);
    __nv_bfloat162 th; th.x = hx; th.y = hy;
    __nv_bfloat162 tl;
    tl.x = __float2bfloat16(x - __bfloat162float(hx));
    tl.y = __float2bfloat16(y - __bfloat162float(hy));
    oh = *(uint32_t*)&th; ol = *(uint32_t*)&tl;
}

// ---------------------------------------------------------------------------
// Conversions (one launch): fp32 -> fp16.
// blocks [0,2048): x -> g_xf ; [2048,3584): Wq/Wk/Wv -> g_wf ;
// [3584,4096): Wo -> g_wof.   8 floats per thread.
// ---------------------------------------------------------------------------
__global__ __launch_bounds__(256)
void conv_all(const float* __restrict__ x,
              const float* __restrict__ Wq, const float* __restrict__ Wk,
              const float* __restrict__ Wv, const float* __restrict__ Wo)
{
    int blk = blockIdx.x;
    const float* src;
    __half* dst;
    int i;
    if (blk < 2048) {
        src = x; dst = g_xf; i = blk * 256 + threadIdx.x;
    } else if (blk < 3584) {
        int w  = (blk - 2048) >> 9;
        int bb = (blk - 2048) & 511;
        src = (w == 0) ? Wq : (w == 1) ? Wk : Wv;
        dst = g_wf + (size_t)w * D_MODEL * D_MODEL;
        i = bb * 256 + threadIdx.x;
    } else {
        src = Wo; dst = g_wof;
        i = (blk - 3584) * 256 + threadIdx.x;
    }

    float4 f0 = ((const float4*)src)[i * 2];
    float4 f1 = ((const float4*)src)[i * 2 + 1];
    __half2 h0 = __floats2half2_rn(f0.x, f0.y);
    __half2 h1 = __floats2half2_rn(f0.z, f0.w);
    __half2 h2 = __floats2half2_rn(f1.x, f1.y);
    __half2 h3 = __floats2half2_rn(f1.z, f1.w);
    uint4 o = { *(uint32_t*)&h0, *(uint32_t*)&h1, *(uint32_t*)&h2, *(uint32_t*)&h3 };
    ((uint4*)dst)[i] = o;
}

// ---------------------------------------------------------------------------
// Single-pass fp16 GEMM: C = A*W^T + bias.  128x128 CTA tile, 8 warps (64x32),
// K-chunks of 32, cp.async 3-stage, 1 sync/chunk, 2 CTAs/SM.
// mode 0 (z=0..2): A=g_xf, W=g_wf+z, C=g_q/g_k/g_v.
// mode 1:          A=g_aof, W=g_wof, C=out_direct, bias=b0.
// ---------------------------------------------------------------------------
#define F16_TILE  8192
#define F16_STAGE 16384
#define F16_NST   3
#define SMEM_F16  (F16_NST * F16_STAGE + 1024)

__global__ __launch_bounds__(256, 2)
void gemm_f16(const float* __restrict__ b0, const float* __restrict__ b1,
              const float* __restrict__ b2, float* __restrict__ out_direct, int mode)
{
    extern __shared__ char dsm_raw[];
    char* sm = (char*)(((uintptr_t)dsm_raw + 1023) & ~(uintptr_t)1023);
    const uint32_t sb = smem_u32(sm);
    const int tid = threadIdx.x, wid = tid >> 5, lane = tid & 31;
    const int bn = blockIdx.x * 128, bm = blockIdx.y * 128, z = blockIdx.z;

    const __half *A, *W;
    if (mode == 0) {
        A = g_xf;
        W = g_wf + (size_t)z * D_MODEL * D_MODEL;
    } else {
        A = g_aof;
        W = g_wof;
    }

    const int r = tid >> 1;
    const int half_ = tid & 1;
    const __half* srcA = A + (size_t)(bm + r) * D_MODEL + half_ * 16;
    const __half* srcW = W + (size_t)(bn + r) * D_MODEL + half_ * 16;
    uint32_t sts_off[2];
#pragma unroll
    for (int s = 0; s < 2; s++) {
        uint32_t u = (uint32_t)(half_ * 2 + s);
        sts_off[s] = (uint32_t)r * 64 + ((u ^ ((uint32_t)r & 3)) << 4);
    }

    const int wm = (wid & 1) * 64;
    const int wn = (wid >> 1) * 32;

    float acc[4][4][4];
#pragma unroll
    for (int mi = 0; mi < 4; mi++)
#pragma unroll
        for (int nj = 0; nj < 4; nj++)
#pragma unroll
            for (int q = 0; q < 4; q++) acc[mi][nj][q] = 0.f;

    const uint32_t lrow = lane & 15;
    const uint32_t lsel = lane >> 4;

    // prologue: chunks 0 and 1 -> stages 0 and 1
#pragma unroll
    for (int pc = 0; pc < 2; pc++) {
        uint32_t stb = sb + (uint32_t)pc * F16_STAGE;
#pragma unroll
        for (int s = 0; s < 2; s++) {
            CPA16(stb + sts_off[s],            srcA + pc * 32 + s * 8);
            CPA16(stb + F16_TILE + sts_off[s], srcW + pc * 32 + s * 8);
        }
        CPA_COMMIT();
    }

    int stage_c = 0;
    int stage_n = 2;
    for (int c = 0; c < 32; c++) {
        if (c == 31) { CPA_WAIT0(); } else { CPA_WAIT1(); }
        __syncthreads();

        if (c + 2 < 32) {
            uint32_t stb = sb + (uint32_t)stage_n * F16_STAGE;
#pragma unroll
            for (int s = 0; s < 2; s++) {
                CPA16(stb + sts_off[s],            srcA + (c + 2) * 32 + s * 8);
                CPA16(stb + F16_TILE + sts_off[s], srcW + (c + 2) * 32 + s * 8);
            }
            CPA_COMMIT();
        }

        const uint32_t stg = sb + (uint32_t)stage_c * F16_STAGE;
#pragma unroll
        for (int kk = 0; kk < 2; kk++) {
            uint32_t bh[2][4];
#pragma unroll
            for (int jp = 0; jp < 2; jp++) {
                uint32_t rw = (uint32_t)(wn + jp * 16) + lrow;
                uint32_t u  = ((uint32_t)kk * 2 + lsel) ^ (rw & 3);
                LDM4(bh[jp], stg + F16_TILE + rw * 64 + (u << 4));
            }
#pragma unroll
            for (int mi = 0; mi < 4; mi++) {
                uint32_t ra = (uint32_t)(wm + mi * 16) + lrow;
                uint32_t u  = ((uint32_t)kk * 2 + lsel) ^ (ra & 3);
                uint32_t ah[4];
                LDM4(ah, stg + ra * 64 + (u << 4));
#pragma unroll
                for (int nj = 0; nj < 4; nj++) {
                    const int jp = nj >> 1, w = nj & 1;
                    MMAF16(acc[mi][nj], ah, bh[jp][w], bh[jp][w + 2]);
                }
            }
        }
        stage_c = (stage_c == F16_NST - 1) ? 0 : stage_c + 1;
        stage_n = (stage_n == F16_NST - 1) ? 0 : stage_n + 1;
    }

    // epilogue
    const float* bias;
    float* C;
    if (mode == 0) {
        bias = (z == 0) ? b0 : ((z == 1) ? b1 : b2);
        C = (z == 0) ? g_q : ((z == 1) ? g_k : g_v);
    } else {
        bias = b0;
        C = out_direct;
    }
#pragma unroll
    for (int mi = 0; mi < 4; mi++) {
        const int orow = bm + wm + mi * 16 + (lane >> 2);
#pragma unroll
        for (int nj = 0; nj < 4; nj++) {
            const int col = bn + wn + nj * 8 + ((lane & 3) << 1);
            float2 o0 = { acc[mi][nj][0] + bias[col], acc[mi][nj][1] + bias[col + 1] };
            float2 o1 = { acc[mi][nj][2] + bias[col], acc[mi][nj][3] + bias[col + 1] };
            *(float2*)&C[(size_t)orow * D_MODEL + col]       = o0;
            *(float2*)&C[(size_t)(orow + 8) * D_MODEL + col] = o1;
        }
    }
}

// ---------------------------------------------------------------------------
// Tensor-core flash attention with fused RoPE (R9 internals, fp16 epilogue).
// ---------------------------------------------------------------------------
__device__ __forceinline__ void rope16(float* x1, float* x2, int s, int cb, float scale) {
#pragma unroll
    for (int i = 0; i < 16; i++) {
        float invf = exp2f(-(float)(cb + i) * (13.2877123795494f / 32.f));
        float ang = (float)s * invf;
        float sn, cs;
        sincosf(ang, &sn, &cs);
        float o1 = (x1[i] * cs - x2[i] * sn) * scale;
        float o2 = (x1[i] * sn + x2[i] * cs) * scale;
        x1[i] = o1; x2[i] = o2;
    }
}

__device__ __forceinline__ void store_hl(char* bh, char* bl, int row, int cb, const float* v) {
#pragma unroll
    for (int i = 0; i < 16; i += 2) {
        uint32_t off = (uint32_t)row * 128 + (uint32_t)(cb + i) * 2;
        off ^= ((uint32_t)row & 7) << 4;
        uint32_t oh, ol;
        split2(v[i], v[i + 1], oh, ol);
        *(uint32_t*)(bh + off) = oh;
        *(uint32_t*)(bl + off) = ol;
    }
}

__global__ __launch_bounds__(128)
void attn_tc()
{
    __shared__ __align__(16) char sdata[49152];
    char* sQH = sdata;          char* sQL = sdata + 8192;
    char* sKH = sdata + 16384;  char* sKL = sdata + 24576;
    char* sVH = sdata + 32768;  char* sVL = sdata + 40960;
    const uint32_t sb = smem_u32(sdata);

    const int tid = threadIdx.x, wid = tid >> 5, lane = tid & 31;
    const int q0 = blockIdx.x * 64, h = blockIdx.y, b = blockIdx.z;
    const float* Qg = g_q + (size_t)b * SEQ * D_MODEL + h * DH;
    const float* Kg = g_k + (size_t)b * SEQ * D_MODEL + h * DH;
    const float* Vg = g_v + (size_t)b * SEQ * D_MODEL + h * DH;

    const int lrw = tid >> 1;
    const int lch = (tid & 1) * 16;

    {
        const float* qp = Qg + (size_t)(q0 + lrw) * D_MODEL;
        float x1[16], x2[16];
#pragma unroll
        for (int i = 0; i < 16; i += 4) {
            *(float4*)(x1 + i) = *(const float4*)(qp + lch + i);
            *(float4*)(x2 + i) = *(const float4*)(qp + lch + 32 + i);
        }
        rope16(x1, x2, q0 + lrw, lch, 0.125f);
        store_hl(sQH, sQL, lrw, lch, x1);
        store_hl(sQH, sQL, lrw, lch + 32, x2);
    }

    const int wq = wid * 16;
    float m0 = -1e30f, m1 = -1e30f, l0 = 0.f, l1 = 0.f;
    float acc[8][4];
#pragma unroll
    for (int nb = 0; nb < 8; nb++)
#pragma unroll
        for (int q = 0; q < 4; q++) acc[nb][q] = 0.f;

    int kv0 = q0 - WIN; if (kv0 < 0) kv0 = 0;
    const int nk = q0 + 64 - kv0;

    const int qg0 = q0 + wq + (lane >> 2);
    const int qg1 = qg0 + 8;

    for (int kb = 0; kb < nk; kb += 64) {
        const int kbase = kv0 + kb;

        __syncthreads();
        {
            const float* kp = Kg + (size_t)(kbase + lrw) * D_MODEL;
            float x1[16], x2[16];
#pragma unroll
            for (int i = 0; i < 16; i += 4) {
                *(float4*)(x1 + i) = *(const float4*)(kp + lch + i);
                *(float4*)(x2 + i) = *(const float4*)(kp + lch + 32 + i);
            }
            rope16(x1, x2, kbase + lrw, lch, 1.0f);
            store_hl(sKH, sKL, lrw, lch, x1);
            store_hl(sKH, sKL, lrw, lch + 32, x2);

            const float* vp = Vg + (size_t)(kbase + lrw) * D_MODEL;
            const int vc = (tid & 1) * 32;
            float va[16], vb[16];
#pragma unroll
            for (int i = 0; i < 16; i += 4) {
                *(float4*)(va + i) = *(const float4*)(vp + vc + i);
                *(float4*)(vb + i) = *(const float4*)(vp + vc + 16 + i);
            }
            store_hl(sVH, sVL, lrw, vc, va);
            store_hl(sVH, sVL, lrw, vc + 16, vb);
        }
        __syncthreads();

        float S[8][4];
#pragma unroll
        for (int nb = 0; nb < 8; nb++)
#pragma unroll
            for (int q = 0; q < 4; q++) S[nb][q] = 0.f;

#pragma unroll
        for (int ks = 0; ks < 4; ks++) {
            const uint32_t acb  = (uint32_t)ks * 32 + ((uint32_t)(lane >> 4) << 4);
            const uint32_t arow = (uint32_t)wq + (lane & 15);
            const uint32_t aoff = arow * 128 + (acb ^ ((arow & 7) << 4));
            uint32_t ah[4], al[4];
            LDM4(ah, sb + aoff);
            LDM4(al, sb + 8192 + aoff);
#pragma unroll
            for (int nb2 = 0; nb2 < 4; nb2++) {
                const uint32_t brow = (uint32_t)nb2 * 16 + (lane & 15);
                const uint32_t boff = brow * 128 + (acb ^ ((brow & 7) << 4));
                uint32_t bh[4], bl[4];
                LDM4(bh, sb + 16384 + boff);
                LDM4(bl, sb + 24576 + boff);
#pragma unroll
                for (int w = 0; w < 2; w++) {
                    const int nb = nb2 * 2 + w;
                    MMA16816(S[nb], ah, bh[w], bh[w + 2]);
                    MMA16816(S[nb], ah, bl[w], bl[w + 2]);
                    MMA16816(S[nb], al, bh[w], bh[w + 2]);
                }
            }
        }

#pragma unroll
        for (int nb = 0; nb < 8; nb++) {
            const int kg = kbase + nb * 8 + ((lane & 3) << 1);
            if (kg     > qg0 || kg     < qg0 - WIN) S[nb][0] = -1e30f;
            if (kg + 1 > qg0 || kg + 1 < qg0 - WIN) S[nb][1] = -1e30f;
            if (kg     > qg1 || kg     < qg1 - WIN) S[nb][2] = -1e30f;
            if (kg + 1 > qg1 || kg + 1 < qg1 - WIN) S[nb][3] = -1e30f;
        }
        float mx0 = -1e30f, mx1 = -1e30f;
#pragma unroll
        for (int nb = 0; nb < 8; nb++) {
            mx0 = fmaxf(mx0, fmaxf(S[nb][0], S[nb][1]));
            mx1 = fmaxf(mx1, fmaxf(S[nb][2], S[nb][3]));
        }
        mx0 = fmaxf(mx0, __shfl_xor_sync(0xffffffffu, mx0, 1));
        mx0 = fmaxf(mx0, __shfl_xor_sync(0xffffffffu, mx0, 2));
        mx1 = fmaxf(mx1, __shfl_xor_sync(0xffffffffu, mx1, 1));
        mx1 = fmaxf(mx1, __shfl_xor_sync(0xffffffffu, mx1, 2));

        const float mn0 = fmaxf(m0, mx0), mn1 = fmaxf(m1, mx1);
        const float e0 = __expf(m0 - mn0), e1 = __expf(m1 - mn1);
        m0 = mn0; m1 = mn1;

        float s0 = 0.f, s1 = 0.f;
#pragma unroll
        for (int nb = 0; nb < 8; nb++) {
            S[nb][0] = __expf(S[nb][0] - m0); s0 += S[nb][0];
            S[nb][1] = __expf(S[nb][1] - m0); s0 += S[nb][1];
            S[nb][2] = __expf(S[nb][2] - m1); s1 += S[nb][2];
            S[nb][3] = __expf(S[nb][3] - m1); s1 += S[nb][3];
        }
        s0 += __shfl_xor_sync(0xffffffffu, s0, 1);
        s0 += __shfl_xor_sync(0xffffffffu, s0, 2);
        s1 += __shfl_xor_sync(0xffffffffu, s1, 1);
        s1 += __shfl_xor_sync(0xffffffffu, s1, 2);
        l0 = l0 * e0 + s0;
        l1 = l1 * e1 + s1;
#pragma unroll
        for (int nb = 0; nb < 8; nb++) {
            acc[nb][0] *= e0; acc[nb][1] *= e0;
            acc[nb][2] *= e1; acc[nb][3] *= e1;
        }

#pragma unroll
        for (int j = 0; j < 4; j++) {
            uint32_t pah[4], pal[4];
            split2(S[2 * j][0],     S[2 * j][1],     pah[0], pal[0]);
            split2(S[2 * j][2],     S[2 * j][3],     pah[1], pal[1]);
            split2(S[2 * j + 1][0], S[2 * j + 1][1], pah[2], pal[2]);
            split2(S[2 * j + 1][2], S[2 * j + 1][3], pah[3], pal[3]);

            const uint32_t vrow = (uint32_t)j * 16 + (lane & 15);
#pragma unroll
            for (int nb2 = 0; nb2 < 4; nb2++) {
                const uint32_t vcb = (uint32_t)nb2 * 32 + ((uint32_t)(lane >> 4) << 4);
                const uint32_t boff = vrow * 128 + (vcb ^ ((vrow & 7) << 4));
                uint32_t vh[4], vl[4];
                LDM4T(vh, sb + 32768 + boff);
                LDM4T(vl, sb + 40960 + boff);
#pragma unroll
                for (int w = 0; w < 2; w++) {
                    const int nb = nb2 * 2 + w;
                    MMA16816(acc[nb], pah, vh[2 * w], vh[2 * w + 1]);
                    MMA16816(acc[nb], pal, vh[2 * w], vh[2 * w + 1]);
                    MMA16816(acc[nb], pah, vl[2 * w], vl[2 * w + 1]);
                }
            }
        }
    }

    // epilogue: normalize, write fp16 to g_aof
    const float inv0 = 1.f / l0, inv1 = 1.f / l1;
#pragma unroll
    for (int nb = 0; nb < 8; nb++) {
        const int col = h * DH + nb * 8 + ((lane & 3) << 1);
        const size_t i0 = ((size_t)b * SEQ + qg0) * D_MODEL + col;
        const size_t i1 = ((size_t)b * SEQ + qg1) * D_MODEL + col;
        __half2 p0 = __floats2half2_rn(acc[nb][0] * inv0, acc[nb][1] * inv0);
        __half2 p1 = __floats2half2_rn(acc[nb][2] * inv1, acc[nb][3] * inv1);
        *(uint32_t*)(g_aof + i0) = *(uint32_t*)&p0;
        *(uint32_t*)(g_aof + i1) = *(uint32_t*)&p1;
    }
}

// ---------------------------------------------------------------------------
extern "C" void kernel_launch(void* const* d_in, const int* in_sizes, int n_in,
                              void* d_out, int out_size)
{
    const float* x  = (const float*)d_in[0];
    const float* Wq = (const float*)d_in[1];
    const float* bq = (const float*)d_in[2];
    const float* Wk = (const float*)d_in[3];
    const float* bk = (const float*)d_in[4];
    const float* Wv = (const float*)d_in[5];
    const float* bv = (const float*)d_in[6];
    const float* Wo = (const float*)d_in[7];
    const float* bo = (const float*)d_in[8];
    float* out = (float*)d_out;

    cudaFuncSetAttribute(gemm_f16, cudaFuncAttributeMaxDynamicSharedMemorySize, SMEM_F16);

    conv_all<<<4096, 256>>>(x, Wq, Wk, Wv, Wo);

    gemm_f16<<<dim3(8, 32, 3), 256, SMEM_F16>>>(bq, bk, bv, nullptr, 0);

    dim3 agrid(SEQ / 64, NHEADS, BATCH);
    attn_tc<<<agrid, 128>>>();

    gemm_f16<<<dim3(8, 32, 1), 256, SMEM_F16>>>(bo, nullptr, nullptr, out, 1);
}

// round 13
// speedup vs baseline: 2.2687x; 1.1736x over previous
#include <cuda_runtime.h>
#include <cuda_bf16.h>
#include <cuda_fp16.h>
#include <math.h>
#include <stdint.h>

#define D_MODEL 1024
#define NHEADS  16
#define DH      64
#define SEQ     2048
#define BATCH   2
#define WIN     128
#define MROWS   (BATCH * SEQ)   // 4096

// ---------------- scratch (static device memory) ----------------
__device__ float g_q [MROWS * D_MODEL];
__device__ float g_k [MROWS * D_MODEL];
__device__ float g_v [MROWS * D_MODEL];

__device__ __half g_xf [MROWS * D_MODEL];          // x,  fp16
__device__ __half g_wf [3 * D_MODEL * D_MODEL];    // Wq/Wk/Wv, fp16
__device__ __half g_wof[D_MODEL * D_MODEL];        // Wo, fp16
__device__ __half g_aof[MROWS * D_MODEL];          // attn out, fp16

// ---------------- PTX helpers ----------------
__device__ __forceinline__ uint32_t smem_u32(const void* p) {
    uint32_t a;
    asm("{ .reg .u64 t; cvta.to.shared.u64 t, %1; cvt.u32.u64 %0, t; }"
        : "=r"(a) : "l"(p));
    return a;
}
#define CPA16(dst, src) \
    asm volatile("cp.async.cg.shared.global [%0], [%1], 16;" :: "r"(dst), "l"(src))
#define CPA_COMMIT() asm volatile("cp.async.commit_group;" ::: "memory")
#define CPA_WAIT1()  asm volatile("cp.async.wait_group 1;" ::: "memory")
#define CPA_WAIT0()  asm volatile("cp.async.wait_group 0;" ::: "memory")

#define LDM4(r, addr) \
    asm volatile("ldmatrix.sync.aligned.m8n8.x4.shared.b16 {%0,%1,%2,%3}, [%4];" \
        : "=r"((r)[0]), "=r"((r)[1]), "=r"((r)[2]), "=r"((r)[3]) : "r"(addr))

#define LDM4T(r, addr) \
    asm volatile("ldmatrix.sync.aligned.m8n8.x4.trans.shared.b16 {%0,%1,%2,%3}, [%4];" \
        : "=r"((r)[0]), "=r"((r)[1]), "=r"((r)[2]), "=r"((r)[3]) : "r"(addr))

#define MMAF16(acc, a, b0, b1) \
    asm volatile("mma.sync.aligned.m16n8k16.row.col.f32.f16.f16.f32 " \
        "{%0,%1,%2,%3}, {%4,%5,%6,%7}, {%8,%9}, {%0,%1,%2,%3};" \
        : "+f"((acc)[0]), "+f"((acc)[1]), "+f"((acc)[2]), "+f"((acc)[3]) \
        : "r"((a)[0]), "r"((a)[1]), "r"((a)[2]), "r"((a)[3]), "r"(b0), "r"(b1))

// ---------------------------------------------------------------------------
// Conversions (one launch): fp32 -> fp16.  8 floats / thread.
// ---------------------------------------------------------------------------
__global__ __launch_bounds__(256)
void conv_all(const float* __restrict__ x,
              const float* __restrict__ Wq, const float* __restrict__ Wk,
              const float* __restrict__ Wv, const float* __restrict__ Wo)
{
    int blk = blockIdx.x;
    const float* src;
    __half* dst;
    int i;
    if (blk < 2048) {
        src = x; dst = g_xf; i = blk * 256 + threadIdx.x;
    } else if (blk < 3584) {
        int w  = (blk - 2048) >> 9;
        int bb = (blk - 2048) & 511;
        src = (w == 0) ? Wq : (w == 1) ? Wk : Wv;
        dst = g_wf + (size_t)w * D_MODEL * D_MODEL;
        i = bb * 256 + threadIdx.x;
    } else {
        src = Wo; dst = g_wof;
        i = (blk - 3584) * 256 + threadIdx.x;
    }

    float4 f0 = ((const float4*)src)[i * 2];
    float4 f1 = ((const float4*)src)[i * 2 + 1];
    __half2 h0 = __floats2half2_rn(f0.x, f0.y);
    __half2 h1 = __floats2half2_rn(f0.z, f0.w);
    __half2 h2 = __floats2half2_rn(f1.x, f1.y);
    __half2 h3 = __floats2half2_rn(f1.z, f1.w);
    uint4 o = { *(uint32_t*)&h0, *(uint32_t*)&h1, *(uint32_t*)&h2, *(uint32_t*)&h3 };
    ((uint4*)dst)[i] = o;
}

// ---------------------------------------------------------------------------
// Single-pass fp16 GEMM: C = A*W^T + bias.  128x128 CTA tile, 8 warps (64x32),
// K-chunks of 64 (16 chunks), 128B rows + 8-unit XOR swizzle,
// cp.async 3-stage, 1 sync/chunk, 2 CTAs/SM.
// ---------------------------------------------------------------------------
#define F16_TILE  16384              // 128 rows x 128 B
#define F16_STAGE 32768
#define F16_NST   3
#define SMEM_F16  (F16_NST * F16_STAGE + 1024)

__global__ __launch_bounds__(256, 2)
void gemm_f16(const float* __restrict__ b0, const float* __restrict__ b1,
              const float* __restrict__ b2, float* __restrict__ out_direct, int mode)
{
    extern __shared__ char dsm_raw[];
    char* sm = (char*)(((uintptr_t)dsm_raw + 1023) & ~(uintptr_t)1023);
    const uint32_t sb = smem_u32(sm);
    const int tid = threadIdx.x, wid = tid >> 5, lane = tid & 31;
    const int bn = blockIdx.x * 128, bm = blockIdx.y * 128, z = blockIdx.z;

    const __half *A, *W;
    if (mode == 0) {
        A = g_xf;
        W = g_wf + (size_t)z * D_MODEL * D_MODEL;
    } else {
        A = g_aof;
        W = g_wof;
    }

    // cp.async: row r = tid/2, half_ = tid&1 owns 32 halves (4 x 16B segs)
    const int r = tid >> 1;
    const int half_ = tid & 1;
    const __half* srcA = A + (size_t)(bm + r) * D_MODEL + half_ * 32;
    const __half* srcW = W + (size_t)(bn + r) * D_MODEL + half_ * 32;
    uint32_t sts_off[4];
#pragma unroll
    for (int s = 0; s < 4; s++) {
        uint32_t u = (uint32_t)(half_ * 4 + s);
        sts_off[s] = (uint32_t)r * 128 + ((u ^ ((uint32_t)r & 7)) << 4);
    }

    const int wm = (wid & 1) * 64;
    const int wn = (wid >> 1) * 32;

    float acc[4][4][4];
#pragma unroll
    for (int mi = 0; mi < 4; mi++)
#pragma unroll
        for (int nj = 0; nj < 4; nj++)
#pragma unroll
            for (int q = 0; q < 4; q++) acc[mi][nj][q] = 0.f;

    const uint32_t lrow = lane & 15;
    const uint32_t lsel = lane >> 4;

    // prologue: chunks 0 and 1 -> stages 0 and 1
#pragma unroll
    for (int pc = 0; pc < 2; pc++) {
        uint32_t stb = sb + (uint32_t)pc * F16_STAGE;
#pragma unroll
        for (int s = 0; s < 4; s++) {
            CPA16(stb + sts_off[s],            srcA + pc * 64 + s * 8);
            CPA16(stb + F16_TILE + sts_off[s], srcW + pc * 64 + s * 8);
        }
        CPA_COMMIT();
    }

    int stage_c = 0;
    int stage_n = 2;
    for (int c = 0; c < 16; c++) {
        if (c == 15) { CPA_WAIT0(); } else { CPA_WAIT1(); }
        __syncthreads();

        if (c + 2 < 16) {
            uint32_t stb = sb + (uint32_t)stage_n * F16_STAGE;
#pragma unroll
            for (int s = 0; s < 4; s++) {
                CPA16(stb + sts_off[s],            srcA + (c + 2) * 64 + s * 8);
                CPA16(stb + F16_TILE + sts_off[s], srcW + (c + 2) * 64 + s * 8);
            }
            CPA_COMMIT();
        }

        const uint32_t stg = sb + (uint32_t)stage_c * F16_STAGE;
#pragma unroll
        for (int kk = 0; kk < 4; kk++) {
            uint32_t bh[2][4];
#pragma unroll
            for (int jp = 0; jp < 2; jp++) {
                uint32_t rw = (uint32_t)(wn + jp * 16) + lrow;
                uint32_t u  = ((uint32_t)kk * 2 + lsel) ^ (rw & 7);
                LDM4(bh[jp], stg + F16_TILE + rw * 128 + (u << 4));
            }
#pragma unroll
            for (int mi = 0; mi < 4; mi++) {
                uint32_t ra = (uint32_t)(wm + mi * 16) + lrow;
                uint32_t u  = ((uint32_t)kk * 2 + lsel) ^ (ra & 7);
                uint32_t ah[4];
                LDM4(ah, stg + ra * 128 + (u << 4));
#pragma unroll
                for (int nj = 0; nj < 4; nj++) {
                    const int jp = nj >> 1, w = nj & 1;
                    MMAF16(acc[mi][nj], ah, bh[jp][w], bh[jp][w + 2]);
                }
            }
        }
        stage_c = (stage_c == F16_NST - 1) ? 0 : stage_c + 1;
        stage_n = (stage_n == F16_NST - 1) ? 0 : stage_n + 1;
    }

    // epilogue
    const float* bias;
    float* C;
    if (mode == 0) {
        bias = (z == 0) ? b0 : ((z == 1) ? b1 : b2);
        C = (z == 0) ? g_q : ((z == 1) ? g_k : g_v);
    } else {
        bias = b0;
        C = out_direct;
    }
#pragma unroll
    for (int mi = 0; mi < 4; mi++) {
        const int orow = bm + wm + mi * 16 + (lane >> 2);
#pragma unroll
        for (int nj = 0; nj < 4; nj++) {
            const int col = bn + wn + nj * 8 + ((lane & 3) << 1);
            float2 o0 = { acc[mi][nj][0] + bias[col], acc[mi][nj][1] + bias[col + 1] };
            float2 o1 = { acc[mi][nj][2] + bias[col], acc[mi][nj][3] + bias[col + 1] };
            *(float2*)&C[(size_t)orow * D_MODEL + col]       = o0;
            *(float2*)&C[(size_t)(orow + 8) * D_MODEL + col] = o1;
        }
    }
}

// ---------------------------------------------------------------------------
// Single-pass fp16 flash attention with fused RoPE.
// CTA = 128 threads (4 warps), 64 queries of one (b,h), K/V chunks of 64.
// smem: sQ/sK/sV fp16 tiles (8KB each), 128B rows, 8-unit XOR swizzle.
// ---------------------------------------------------------------------------
__device__ __forceinline__ void rope16(float* x1, float* x2, int s, int cb, float scale) {
#pragma unroll
    for (int i = 0; i < 16; i++) {
        float invf = exp2f(-(float)(cb + i) * (13.2877123795494f / 32.f));
        float ang = (float)s * invf;
        float sn, cs;
        sincosf(ang, &sn, &cs);
        float o1 = (x1[i] * cs - x2[i] * sn) * scale;
        float o2 = (x1[i] * sn + x2[i] * cs) * scale;
        x1[i] = o1; x2[i] = o2;
    }
}

__device__ __forceinline__ void store_h(char* base, int row, int cb, const float* v) {
#pragma unroll
    for (int i = 0; i < 16; i += 2) {
        uint32_t off = (uint32_t)row * 128 + (uint32_t)(cb + i) * 2;
        off ^= ((uint32_t)row & 7) << 4;
        __half2 p = __floats2half2_rn(v[i], v[i + 1]);
        *(uint32_t*)(base + off) = *(uint32_t*)&p;
    }
}

__global__ __launch_bounds__(128)
void attn_tc()
{
    __shared__ __align__(16) char sdata[24576];
    char* sQ = sdata;            // 64 x 64 fp16
    char* sK = sdata + 8192;
    char* sV = sdata + 16384;
    const uint32_t sb = smem_u32(sdata);

    const int tid = threadIdx.x, wid = tid >> 5, lane = tid & 31;
    const int q0 = blockIdx.x * 64, h = blockIdx.y, b = blockIdx.z;
    const float* Qg = g_q + (size_t)b * SEQ * D_MODEL + h * DH;
    const float* Kg = g_k + (size_t)b * SEQ * D_MODEL + h * DH;
    const float* Vg = g_v + (size_t)b * SEQ * D_MODEL + h * DH;

    const int lrw = tid >> 1;
    const int lch = (tid & 1) * 16;

    // ---- Q: load fp32, rope + 0.125 scale, store fp16 ----
    {
        const float* qp = Qg + (size_t)(q0 + lrw) * D_MODEL;
        float x1[16], x2[16];
#pragma unroll
        for (int i = 0; i < 16; i += 4) {
            *(float4*)(x1 + i) = *(const float4*)(qp + lch + i);
            *(float4*)(x2 + i) = *(const float4*)(qp + lch + 32 + i);
        }
        rope16(x1, x2, q0 + lrw, lch, 0.125f);
        store_h(sQ, lrw, lch, x1);
        store_h(sQ, lrw, lch + 32, x2);
    }

    const int wq = wid * 16;
    float m0 = -1e30f, m1 = -1e30f, l0 = 0.f, l1 = 0.f;
    float acc[8][4];
#pragma unroll
    for (int nb = 0; nb < 8; nb++)
#pragma unroll
        for (int q = 0; q < 4; q++) acc[nb][q] = 0.f;

    int kv0 = q0 - WIN; if (kv0 < 0) kv0 = 0;
    const int nk = q0 + 64 - kv0;

    const int qg0 = q0 + wq + (lane >> 2);
    const int qg1 = qg0 + 8;

    for (int kb = 0; kb < nk; kb += 64) {
        const int kbase = kv0 + kb;

        __syncthreads();
        // ---- K: rope + store fp16; V: store fp16 ----
        {
            const float* kp = Kg + (size_t)(kbase + lrw) * D_MODEL;
            float x1[16], x2[16];
#pragma unroll
            for (int i = 0; i < 16; i += 4) {
                *(float4*)(x1 + i) = *(const float4*)(kp + lch + i);
                *(float4*)(x2 + i) = *(const float4*)(kp + lch + 32 + i);
            }
            rope16(x1, x2, kbase + lrw, lch, 1.0f);
            store_h(sK, lrw, lch, x1);
            store_h(sK, lrw, lch + 32, x2);

            const float* vp = Vg + (size_t)(kbase + lrw) * D_MODEL;
            const int vc = (tid & 1) * 32;
            float va[16], vb[16];
#pragma unroll
            for (int i = 0; i < 16; i += 4) {
                *(float4*)(va + i) = *(const float4*)(vp + vc + i);
                *(float4*)(vb + i) = *(const float4*)(vp + vc + 16 + i);
            }
            store_h(sV, lrw, vc, va);
            store_h(sV, lrw, vc + 16, vb);
        }
        __syncthreads();

        // ---- S = Q K^T (single fp16 pass) ----
        float S[8][4];
#pragma unroll
        for (int nb = 0; nb < 8; nb++)
#pragma unroll
            for (int q = 0; q < 4; q++) S[nb][q] = 0.f;

#pragma unroll
        for (int ks = 0; ks < 4; ks++) {
            const uint32_t acb  = (uint32_t)ks * 32 + ((uint32_t)(lane >> 4) << 4);
            const uint32_t arow = (uint32_t)wq + (lane & 15);
            const uint32_t aoff = arow * 128 + (acb ^ ((arow & 7) << 4));
            uint32_t ah[4];
            LDM4(ah, sb + aoff);
#pragma unroll
            for (int nb2 = 0; nb2 < 4; nb2++) {
                const uint32_t brow = (uint32_t)nb2 * 16 + (lane & 15);
                const uint32_t boff = brow * 128 + (acb ^ ((brow & 7) << 4));
                uint32_t bh[4];
                LDM4(bh, sb + 8192 + boff);
                MMAF16(S[nb2 * 2],     ah, bh[0], bh[2]);
                MMAF16(S[nb2 * 2 + 1], ah, bh[1], bh[3]);
            }
        }

        // ---- mask + online softmax ----
#pragma unroll
        for (int nb = 0; nb < 8; nb++) {
            const int kg = kbase + nb * 8 + ((lane & 3) << 1);
            if (kg     > qg0 || kg     < qg0 - WIN) S[nb][0] = -1e30f;
            if (kg + 1 > qg0 || kg + 1 < qg0 - WIN) S[nb][1] = -1e30f;
            if (kg     > qg1 || kg     < qg1 - WIN) S[nb][2] = -1e30f;
            if (kg + 1 > qg1 || kg + 1 < qg1 - WIN) S[nb][3] = -1e30f;
        }
        float mx0 = -1e30f, mx1 = -1e30f;
#pragma unroll
        for (int nb = 0; nb < 8; nb++) {
            mx0 = fmaxf(mx0, fmaxf(S[nb][0], S[nb][1]));
            mx1 = fmaxf(mx1, fmaxf(S[nb][2], S[nb][3]));
        }
        mx0 = fmaxf(mx0, __shfl_xor_sync(0xffffffffu, mx0, 1));
        mx0 = fmaxf(mx0, __shfl_xor_sync(0xffffffffu, mx0, 2));
        mx1 = fmaxf(mx1, __shfl_xor_sync(0xffffffffu, mx1, 1));
        mx1 = fmaxf(mx1, __shfl_xor_sync(0xffffffffu, mx1, 2));

        const float mn0 = fmaxf(m0, mx0), mn1 = fmaxf(m1, mx1);
        const float e0 = __expf(m0 - mn0), e1 = __expf(m1 - mn1);
        m0 = mn0; m1 = mn1;

        float s0 = 0.f, s1 = 0.f;
#pragma unroll
        for (int nb = 0; nb < 8; nb++) {
            S[nb][0] = __expf(S[nb][0] - m0); s0 += S[nb][0];
            S[nb][1] = __expf(S[nb][1] - m0); s0 += S[nb][1];
            S[nb][2] = __expf(S[nb][2] - m1); s1 += S[nb][2];
            S[nb][3] = __expf(S[nb][3] - m1); s1 += S[nb][3];
        }
        s0 += __shfl_xor_sync(0xffffffffu, s0, 1);
        s0 += __shfl_xor_sync(0xffffffffu, s0, 2);
        s1 += __shfl_xor_sync(0xffffffffu, s1, 1);
        s1 += __shfl_xor_sync(0xffffffffu, s1, 2);
        l0 = l0 * e0 + s0;
        l1 = l1 * e1 + s1;
#pragma unroll
        for (int nb = 0; nb < 8; nb++) {
            acc[nb][0] *= e0; acc[nb][1] *= e0;
            acc[nb][2] *= e1; acc[nb][3] *= e1;
        }

        // ---- O += P V (single fp16 pass) ----
#pragma unroll
        for (int j = 0; j < 4; j++) {
            uint32_t pa[4];
            __half2 p0 = __floats2half2_rn(S[2 * j][0],     S[2 * j][1]);
            __half2 p1 = __floats2half2_rn(S[2 * j][2],     S[2 * j][3]);
            __half2 p2 = __floats2half2_rn(S[2 * j + 1][0], S[2 * j + 1][1]);
            __half2 p3 = __floats2half2_rn(S[2 * j + 1][2], S[2 * j + 1][3]);
            pa[0] = *(uint32_t*)&p0; pa[1] = *(uint32_t*)&p1;
            pa[2] = *(uint32_t*)&p2; pa[3] = *(uint32_t*)&p3;

            const uint32_t vrow = (uint32_t)j * 16 + (lane & 15);
#pragma unroll
            for (int nb2 = 0; nb2 < 4; nb2++) {
                const uint32_t vcb = (uint32_t)nb2 * 32 + ((uint32_t)(lane >> 4) << 4);
                const uint32_t boff = vrow * 128 + (vcb ^ ((vrow & 7) << 4));
                uint32_t vh[4];
                LDM4T(vh, sb + 16384 + boff);
                MMAF16(acc[nb2 * 2],     pa, vh[0], vh[1]);
                MMAF16(acc[nb2 * 2 + 1], pa, vh[2], vh[3]);
            }
        }
    }

    // epilogue: normalize, write fp16 to g_aof
    const float inv0 = 1.f / l0, inv1 = 1.f / l1;
#pragma unroll
    for (int nb = 0; nb < 8; nb++) {
        const int col = h * DH + nb * 8 + ((lane & 3) << 1);
        const size_t i0 = ((size_t)b * SEQ + qg0) * D_MODEL + col;
        const size_t i1 = ((size_t)b * SEQ + qg1) * D_MODEL + col;
        __half2 p0 = __floats2half2_rn(acc[nb][0] * inv0, acc[nb][1] * inv0);
        __half2 p1 = __floats2half2_rn(acc[nb][2] * inv1, acc[nb][3] * inv1);
        *(uint32_t*)(g_aof + i0) = *(uint32_t*)&p0;
        *(uint32_t*)(g_aof + i1) = *(uint32_t*)&p1;
    }
}

// ---------------------------------------------------------------------------
extern "C" void kernel_launch(void* const* d_in, const int* in_sizes, int n_in,
                              void* d_out, int out_size)
{
    const float* x  = (const float*)d_in[0];
    const float* Wq = (const float*)d_in[1];
    const float* bq = (const float*)d_in[2];
    const float* Wk = (const float*)d_in[3];
    const float* bk = (const float*)d_in[4];
    const float* Wv = (const float*)d_in[5];
    const float* bv = (const float*)d_in[6];
    const float* Wo = (const float*)d_in[7];
    const float* bo = (const float*)d_in[8];
    float* out = (float*)d_out;

    cudaFuncSetAttribute(gemm_f16, cudaFuncAttributeMaxDynamicSharedMemorySize, SMEM_F16);

    conv_all<<<4096, 256>>>(x, Wq, Wk, Wv, Wo);

    gemm_f16<<<dim3(8, 32, 3), 256, SMEM_F16>>>(bq, bk, bv, nullptr, 0);

    dim3 agrid(SEQ / 64, NHEADS, BATCH);
    attn_tc<<<agrid, 128>>>();

    gemm_f16<<<dim3(8, 32, 1), 256, SMEM_F16>>>(bo, nullptr, nullptr, out, 1);
}

// round 14
// speedup vs baseline: 2.2796x; 1.0048x over previous
#include <cuda_runtime.h>
#include <cuda_bf16.h>
#include <cuda_fp16.h>
#include <math.h>
#include <stdint.h>

#define D_MODEL 1024
#define NHEADS  16
#define DH      64
#define SEQ     2048
#define BATCH   2
#define WIN     128
#define MROWS   (BATCH * SEQ)   // 4096

// ---------------- scratch (static device memory) ----------------
__device__ float g_q [MROWS * D_MODEL];
__device__ float g_k [MROWS * D_MODEL];
__device__ float g_v [MROWS * D_MODEL];

__device__ __half g_xf [MROWS * D_MODEL];          // x,  fp16
__device__ __half g_wf [3 * D_MODEL * D_MODEL];    // Wq/Wk/Wv, fp16
__device__ __half g_wof[D_MODEL * D_MODEL];        // Wo, fp16
__device__ __half g_aof[MROWS * D_MODEL];          // attn out, fp16

// ---------------- PTX helpers ----------------
__device__ __forceinline__ uint32_t smem_u32(const void* p) {
    uint32_t a;
    asm("{ .reg .u64 t; cvta.to.shared.u64 t, %1; cvt.u32.u64 %0, t; }"
        : "=r"(a) : "l"(p));
    return a;
}
#define CPA16(dst, src) \
    asm volatile("cp.async.cg.shared.global [%0], [%1], 16;" :: "r"(dst), "l"(src))
#define CPA_COMMIT() asm volatile("cp.async.commit_group;" ::: "memory")
#define CPA_WAIT1()  asm volatile("cp.async.wait_group 1;" ::: "memory")
#define CPA_WAIT0()  asm volatile("cp.async.wait_group 0;" ::: "memory")

#define LDM4(r, addr) \
    asm volatile("ldmatrix.sync.aligned.m8n8.x4.shared.b16 {%0,%1,%2,%3}, [%4];" \
        : "=r"((r)[0]), "=r"((r)[1]), "=r"((r)[2]), "=r"((r)[3]) : "r"(addr))

#define LDM4T(r, addr) \
    asm volatile("ldmatrix.sync.aligned.m8n8.x4.trans.shared.b16 {%0,%1,%2,%3}, [%4];" \
        : "=r"((r)[0]), "=r"((r)[1]), "=r"((r)[2]), "=r"((r)[3]) : "r"(addr))

#define MMAF16(acc, a, b0, b1) \
    asm volatile("mma.sync.aligned.m16n8k16.row.col.f32.f16.f16.f32 " \
        "{%0,%1,%2,%3}, {%4,%5,%6,%7}, {%8,%9}, {%0,%1,%2,%3};" \
        : "+f"((acc)[0]), "+f"((acc)[1]), "+f"((acc)[2]), "+f"((acc)[3]) \
        : "r"((a)[0]), "r"((a)[1]), "r"((a)[2]), "r"((a)[3]), "r"(b0), "r"(b1))

// ---------------------------------------------------------------------------
// Conversions (one launch): fp32 -> fp16.  8 floats / thread.
// ---------------------------------------------------------------------------
__global__ __launch_bounds__(256)
void conv_all(const float* __restrict__ x,
              const float* __restrict__ Wq, const float* __restrict__ Wk,
              const float* __restrict__ Wv, const float* __restrict__ Wo)
{
    int blk = blockIdx.x;
    const float* src;
    __half* dst;
    int i;
    if (blk < 2048) {
        src = x; dst = g_xf; i = blk * 256 + threadIdx.x;
    } else if (blk < 3584) {
        int w  = (blk - 2048) >> 9;
        int bb = (blk - 2048) & 511;
        src = (w == 0) ? Wq : (w == 1) ? Wk : Wv;
        dst = g_wf + (size_t)w * D_MODEL * D_MODEL;
        i = bb * 256 + threadIdx.x;
    } else {
        src = Wo; dst = g_wof;
        i = (blk - 3584) * 256 + threadIdx.x;
    }

    float4 f0 = ((const float4*)src)[i * 2];
    float4 f1 = ((const float4*)src)[i * 2 + 1];
    __half2 h0 = __floats2half2_rn(f0.x, f0.y);
    __half2 h1 = __floats2half2_rn(f0.z, f0.w);
    __half2 h2 = __floats2half2_rn(f1.x, f1.y);
    __half2 h3 = __floats2half2_rn(f1.z, f1.w);
    uint4 o = { *(uint32_t*)&h0, *(uint32_t*)&h1, *(uint32_t*)&h2, *(uint32_t*)&h3 };
    ((uint4*)dst)[i] = o;
}

// ---------------------------------------------------------------------------
// Single-pass fp16 GEMM: C = A*W^T + bias.  128x128 CTA tile, 8 warps (64x32),
// K-chunks of 64, cp.async 3-stage, 1 sync/chunk, 2 CTAs/SM.
// R14: fragment software pipeline inside each kk (static indices):
//      LDSM B0,B1,A0,A1 -> MMA(mi0)+LDSM A2 -> MMA(mi1)+LDSM A3 -> MMA(mi2,mi3)
// ---------------------------------------------------------------------------
#define F16_TILE  16384              // 128 rows x 128 B
#define F16_STAGE 32768
#define F16_NST   3
#define SMEM_F16  (F16_NST * F16_STAGE + 1024)

__global__ __launch_bounds__(256, 2)
void gemm_f16(const float* __restrict__ b0, const float* __restrict__ b1,
              const float* __restrict__ b2, float* __restrict__ out_direct, int mode)
{
    extern __shared__ char dsm_raw[];
    char* sm = (char*)(((uintptr_t)dsm_raw + 1023) & ~(uintptr_t)1023);
    const uint32_t sb = smem_u32(sm);
    const int tid = threadIdx.x, wid = tid >> 5, lane = tid & 31;
    const int bn = blockIdx.x * 128, bm = blockIdx.y * 128, z = blockIdx.z;

    const __half *A, *W;
    if (mode == 0) {
        A = g_xf;
        W = g_wf + (size_t)z * D_MODEL * D_MODEL;
    } else {
        A = g_aof;
        W = g_wof;
    }

    const int r = tid >> 1;
    const int half_ = tid & 1;
    const __half* srcA = A + (size_t)(bm + r) * D_MODEL + half_ * 32;
    const __half* srcW = W + (size_t)(bn + r) * D_MODEL + half_ * 32;
    uint32_t sts_off[4];
#pragma unroll
    for (int s = 0; s < 4; s++) {
        uint32_t u = (uint32_t)(half_ * 4 + s);
        sts_off[s] = (uint32_t)r * 128 + ((u ^ ((uint32_t)r & 7)) << 4);
    }

    const int wm = (wid & 1) * 64;
    const int wn = (wid >> 1) * 32;

    float acc[4][4][4];
#pragma unroll
    for (int mi = 0; mi < 4; mi++)
#pragma unroll
        for (int nj = 0; nj < 4; nj++)
#pragma unroll
            for (int q = 0; q < 4; q++) acc[mi][nj][q] = 0.f;

    const uint32_t lrow = lane & 15;
    const uint32_t lsel = lane >> 4;

    // prologue: chunks 0 and 1 -> stages 0 and 1
#pragma unroll
    for (int pc = 0; pc < 2; pc++) {
        uint32_t stb = sb + (uint32_t)pc * F16_STAGE;
#pragma unroll
        for (int s = 0; s < 4; s++) {
            CPA16(stb + sts_off[s],            srcA + pc * 64 + s * 8);
            CPA16(stb + F16_TILE + sts_off[s], srcW + pc * 64 + s * 8);
        }
        CPA_COMMIT();
    }

    int stage_c = 0;
    int stage_n = 2;
    for (int c = 0; c < 16; c++) {
        if (c == 15) { CPA_WAIT0(); } else { CPA_WAIT1(); }
        __syncthreads();

        if (c + 2 < 16) {
            uint32_t stb = sb + (uint32_t)stage_n * F16_STAGE;
#pragma unroll
            for (int s = 0; s < 4; s++) {
                CPA16(stb + sts_off[s],            srcA + (c + 2) * 64 + s * 8);
                CPA16(stb + F16_TILE + sts_off[s], srcW + (c + 2) * 64 + s * 8);
            }
            CPA_COMMIT();
        }

        const uint32_t stg = sb + (uint32_t)stage_c * F16_STAGE;
#pragma unroll
        for (int kk = 0; kk < 4; kk++) {
            // ---- fragment addresses (all static layout math) ----
            const uint32_t kb = (uint32_t)kk * 2 + lsel;
            uint32_t rw0 = (uint32_t)wn + lrow;
            uint32_t rw1 = (uint32_t)(wn + 16) + lrow;
            uint32_t ra0 = (uint32_t)wm + lrow;
            uint32_t ra1 = (uint32_t)(wm + 16) + lrow;
            uint32_t ra2 = (uint32_t)(wm + 32) + lrow;
            uint32_t ra3 = (uint32_t)(wm + 48) + lrow;

            uint32_t bh0[4], bh1[4], a0[4], a1[4], a2[4], a3[4];
            // front-load: both B frags + first two A frags
            LDM4(bh0, stg + F16_TILE + rw0 * 128 + ((kb ^ (rw0 & 7)) << 4));
            LDM4(bh1, stg + F16_TILE + rw1 * 128 + ((kb ^ (rw1 & 7)) << 4));
            LDM4(a0, stg + ra0 * 128 + ((kb ^ (ra0 & 7)) << 4));
            LDM4(a1, stg + ra1 * 128 + ((kb ^ (ra1 & 7)) << 4));

            // mi0 MMAs; prefetch A2 behind them
            MMAF16(acc[0][0], a0, bh0[0], bh0[2]);
            MMAF16(acc[0][1], a0, bh0[1], bh0[3]);
            LDM4(a2, stg + ra2 * 128 + ((kb ^ (ra2 & 7)) << 4));
            MMAF16(acc[0][2], a0, bh1[0], bh1[2]);
            MMAF16(acc[0][3], a0, bh1[1], bh1[3]);

            // mi1 MMAs; prefetch A3
            MMAF16(acc[1][0], a1, bh0[0], bh0[2]);
            MMAF16(acc[1][1], a1, bh0[1], bh0[3]);
            LDM4(a3, stg + ra3 * 128 + ((kb ^ (ra3 & 7)) << 4));
            MMAF16(acc[1][2], a1, bh1[0], bh1[2]);
            MMAF16(acc[1][3], a1, bh1[1], bh1[3]);

            // mi2, mi3 MMAs (operands long since in flight)
            MMAF16(acc[2][0], a2, bh0[0], bh0[2]);
            MMAF16(acc[2][1], a2, bh0[1], bh0[3]);
            MMAF16(acc[2][2], a2, bh1[0], bh1[2]);
            MMAF16(acc[2][3], a2, bh1[1], bh1[3]);
            MMAF16(acc[3][0], a3, bh0[0], bh0[2]);
            MMAF16(acc[3][1], a3, bh0[1], bh0[3]);
            MMAF16(acc[3][2], a3, bh1[0], bh1[2]);
            MMAF16(acc[3][3], a3, bh1[1], bh1[3]);
        }
        stage_c = (stage_c == F16_NST - 1) ? 0 : stage_c + 1;
        stage_n = (stage_n == F16_NST - 1) ? 0 : stage_n + 1;
    }

    // epilogue
    const float* bias;
    float* C;
    if (mode == 0) {
        bias = (z == 0) ? b0 : ((z == 1) ? b1 : b2);
        C = (z == 0) ? g_q : ((z == 1) ? g_k : g_v);
    } else {
        bias = b0;
        C = out_direct;
    }
#pragma unroll
    for (int mi = 0; mi < 4; mi++) {
        const int orow = bm + wm + mi * 16 + (lane >> 2);
#pragma unroll
        for (int nj = 0; nj < 4; nj++) {
            const int col = bn + wn + nj * 8 + ((lane & 3) << 1);
            float2 o0 = { acc[mi][nj][0] + bias[col], acc[mi][nj][1] + bias[col + 1] };
            float2 o1 = { acc[mi][nj][2] + bias[col], acc[mi][nj][3] + bias[col + 1] };
            *(float2*)&C[(size_t)orow * D_MODEL + col]       = o0;
            *(float2*)&C[(size_t)(orow + 8) * D_MODEL + col] = o1;
        }
    }
}

// ---------------------------------------------------------------------------
// Single-pass fp16 flash attention with fused RoPE (unchanged from R13).
// ---------------------------------------------------------------------------
__device__ __forceinline__ void rope16(float* x1, float* x2, int s, int cb, float scale) {
#pragma unroll
    for (int i = 0; i < 16; i++) {
        float invf = exp2f(-(float)(cb + i) * (13.2877123795494f / 32.f));
        float ang = (float)s * invf;
        float sn, cs;
        sincosf(ang, &sn, &cs);
        float o1 = (x1[i] * cs - x2[i] * sn) * scale;
        float o2 = (x1[i] * sn + x2[i] * cs) * scale;
        x1[i] = o1; x2[i] = o2;
    }
}

__device__ __forceinline__ void store_h(char* base, int row, int cb, const float* v) {
#pragma unroll
    for (int i = 0; i < 16; i += 2) {
        uint32_t off = (uint32_t)row * 128 + (uint32_t)(cb + i) * 2;
        off ^= ((uint32_t)row & 7) << 4;
        __half2 p = __floats2half2_rn(v[i], v[i + 1]);
        *(uint32_t*)(base + off) = *(uint32_t*)&p;
    }
}

__global__ __launch_bounds__(128)
void attn_tc()
{
    __shared__ __align__(16) char sdata[24576];
    char* sQ = sdata;
    char* sK = sdata + 8192;
    char* sV = sdata + 16384;
    const uint32_t sb = smem_u32(sdata);

    const int tid = threadIdx.x, wid = tid >> 5, lane = tid & 31;
    const int q0 = blockIdx.x * 64, h = blockIdx.y, b = blockIdx.z;
    const float* Qg = g_q + (size_t)b * SEQ * D_MODEL + h * DH;
    const float* Kg = g_k + (size_t)b * SEQ * D_MODEL + h * DH;
    const float* Vg = g_v + (size_t)b * SEQ * D_MODEL + h * DH;

    const int lrw = tid >> 1;
    const int lch = (tid & 1) * 16;

    {
        const float* qp = Qg + (size_t)(q0 + lrw) * D_MODEL;
        float x1[16], x2[16];
#pragma unroll
        for (int i = 0; i < 16; i += 4) {
            *(float4*)(x1 + i) = *(const float4*)(qp + lch + i);
            *(float4*)(x2 + i) = *(const float4*)(qp + lch + 32 + i);
        }
        rope16(x1, x2, q0 + lrw, lch, 0.125f);
        store_h(sQ, lrw, lch, x1);
        store_h(sQ, lrw, lch + 32, x2);
    }

    const int wq = wid * 16;
    float m0 = -1e30f, m1 = -1e30f, l0 = 0.f, l1 = 0.f;
    float acc[8][4];
#pragma unroll
    for (int nb = 0; nb < 8; nb++)
#pragma unroll
        for (int q = 0; q < 4; q++) acc[nb][q] = 0.f;

    int kv0 = q0 - WIN; if (kv0 < 0) kv0 = 0;
    const int nk = q0 + 64 - kv0;

    const int qg0 = q0 + wq + (lane >> 2);
    const int qg1 = qg0 + 8;

    for (int kb = 0; kb < nk; kb += 64) {
        const int kbase = kv0 + kb;

        __syncthreads();
        {
            const float* kp = Kg + (size_t)(kbase + lrw) * D_MODEL;
            float x1[16], x2[16];
#pragma unroll
            for (int i = 0; i < 16; i += 4) {
                *(float4*)(x1 + i) = *(const float4*)(kp + lch + i);
                *(float4*)(x2 + i) = *(const float4*)(kp + lch + 32 + i);
            }
            rope16(x1, x2, kbase + lrw, lch, 1.0f);
            store_h(sK, lrw, lch, x1);
            store_h(sK, lrw, lch + 32, x2);

            const float* vp = Vg + (size_t)(kbase + lrw) * D_MODEL;
            const int vc = (tid & 1) * 32;
            float va[16], vb[16];
#pragma unroll
            for (int i = 0; i < 16; i += 4) {
                *(float4*)(va + i) = *(const float4*)(vp + vc + i);
                *(float4*)(vb + i) = *(const float4*)(vp + vc + 16 + i);
            }
            store_h(sV, lrw, vc, va);
            store_h(sV, lrw, vc + 16, vb);
        }
        __syncthreads();

        float S[8][4];
#pragma unroll
        for (int nb = 0; nb < 8; nb++)
#pragma unroll
            for (int q = 0; q < 4; q++) S[nb][q] = 0.f;

#pragma unroll
        for (int ks = 0; ks < 4; ks++) {
            const uint32_t acb  = (uint32_t)ks * 32 + ((uint32_t)(lane >> 4) << 4);
            const uint32_t arow = (uint32_t)wq + (lane & 15);
            const uint32_t aoff = arow * 128 + (acb ^ ((arow & 7) << 4));
            uint32_t ah[4];
            LDM4(ah, sb + aoff);
#pragma unroll
            for (int nb2 = 0; nb2 < 4; nb2++) {
                const uint32_t brow = (uint32_t)nb2 * 16 + (lane & 15);
                const uint32_t boff = brow * 128 + (acb ^ ((brow & 7) << 4));
                uint32_t bh[4];
                LDM4(bh, sb + 8192 + boff);
                MMAF16(S[nb2 * 2],     ah, bh[0], bh[2]);
                MMAF16(S[nb2 * 2 + 1], ah, bh[1], bh[3]);
            }
        }

#pragma unroll
        for (int nb = 0; nb < 8; nb++) {
            const int kg = kbase + nb * 8 + ((lane & 3) << 1);
            if (kg     > qg0 || kg     < qg0 - WIN) S[nb][0] = -1e30f;
            if (kg + 1 > qg0 || kg + 1 < qg0 - WIN) S[nb][1] = -1e30f;
            if (kg     > qg1 || kg     < qg1 - WIN) S[nb][2] = -1e30f;
            if (kg + 1 > qg1 || kg + 1 < qg1 - WIN) S[nb][3] = -1e30f;
        }
        float mx0 = -1e30f, mx1 = -1e30f;
#pragma unroll
        for (int nb = 0; nb < 8; nb++) {
            mx0 = fmaxf(mx0, fmaxf(S[nb][0], S[nb][1]));
            mx1 = fmaxf(mx1, fmaxf(S[nb][2], S[nb][3]));
        }
        mx0 = fmaxf(mx0, __shfl_xor_sync(0xffffffffu, mx0, 1));
        mx0 = fmaxf(mx0, __shfl_xor_sync(0xffffffffu, mx0, 2));
        mx1 = fmaxf(mx1, __shfl_xor_sync(0xffffffffu, mx1, 1));
        mx1 = fmaxf(mx1, __shfl_xor_sync(0xffffffffu, mx1, 2));

        const float mn0 = fmaxf(m0, mx0), mn1 = fmaxf(m1, mx1);
        const float e0 = __expf(m0 - mn0), e1 = __expf(m1 - mn1);
        m0 = mn0; m1 = mn1;

        float s0 = 0.f, s1 = 0.f;
#pragma unroll
        for (int nb = 0; nb < 8; nb++) {
            S[nb][0] = __expf(S[nb][0] - m0); s0 += S[nb][0];
            S[nb][1] = __expf(S[nb][1] - m0); s0 += S[nb][1];
            S[nb][2] = __expf(S[nb][2] - m1); s1 += S[nb][2];
            S[nb][3] = __expf(S[nb][3] - m1); s1 += S[nb][3];
        }
        s0 += __shfl_xor_sync(0xffffffffu, s0, 1);
        s0 += __shfl_xor_sync(0xffffffffu, s0, 2);
        s1 += __shfl_xor_sync(0xffffffffu, s1, 1);
        s1 += __shfl_xor_sync(0xffffffffu, s1, 2);
        l0 = l0 * e0 + s0;
        l1 = l1 * e1 + s1;
#pragma unroll
        for (int nb = 0; nb < 8; nb++) {
            acc[nb][0] *= e0; acc[nb][1] *= e0;
            acc[nb][2] *= e1; acc[nb][3] *= e1;
        }

#pragma unroll
        for (int j = 0; j < 4; j++) {
            uint32_t pa[4];
            __half2 p0 = __floats2half2_rn(S[2 * j][0],     S[2 * j][1]);
            __half2 p1 = __floats2half2_rn(S[2 * j][2],     S[2 * j][3]);
            __half2 p2 = __floats2half2_rn(S[2 * j + 1][0], S[2 * j + 1][1]);
            __half2 p3 = __floats2half2_rn(S[2 * j + 1][2], S[2 * j + 1][3]);
            pa[0] = *(uint32_t*)&p0; pa[1] = *(uint32_t*)&p1;
            pa[2] = *(uint32_t*)&p2; pa[3] = *(uint32_t*)&p3;

            const uint32_t vrow = (uint32_t)j * 16 + (lane & 15);
#pragma unroll
            for (int nb2 = 0; nb2 < 4; nb2++) {
                const uint32_t vcb = (uint32_t)nb2 * 32 + ((uint32_t)(lane >> 4) << 4);
                const uint32_t boff = vrow * 128 + (vcb ^ ((vrow & 7) << 4));
                uint32_t vh[4];
                LDM4T(vh, sb + 16384 + boff);
                MMAF16(acc[nb2 * 2],     pa, vh[0], vh[1]);
                MMAF16(acc[nb2 * 2 + 1], pa, vh[2], vh[3]);
            }
        }
    }

    const float inv0 = 1.f / l0, inv1 = 1.f / l1;
#pragma unroll
    for (int nb = 0; nb < 8; nb++) {
        const int col = h * DH + nb * 8 + ((lane & 3) << 1);
        const size_t i0 = ((size_t)b * SEQ + qg0) * D_MODEL + col;
        const size_t i1 = ((size_t)b * SEQ + qg1) * D_MODEL + col;
        __half2 p0 = __floats2half2_rn(acc[nb][0] * inv0, acc[nb][1] * inv0);
        __half2 p1 = __floats2half2_rn(acc[nb][2] * inv1, acc[nb][3] * inv1);
        *(uint32_t*)(g_aof + i0) = *(uint32_t*)&p0;
        *(uint32_t*)(g_aof + i1) = *(uint32_t*)&p1;
    }
}

// ---------------------------------------------------------------------------
extern "C" void kernel_launch(void* const* d_in, const int* in_sizes, int n_in,
                              void* d_out, int out_size)
{
    const float* x  = (const float*)d_in[0];
    const float* Wq = (const float*)d_in[1];
    const float* bq = (const float*)d_in[2];
    const float* Wk = (const float*)d_in[3];
    const float* bk = (const float*)d_in[4];
    const float* Wv = (const float*)d_in[5];
    const float* bv = (const float*)d_in[6];
    const float* Wo = (const float*)d_in[7];
    const float* bo = (const float*)d_in[8];
    float* out = (float*)d_out;

    cudaFuncSetAttribute(gemm_f16, cudaFuncAttributeMaxDynamicSharedMemorySize, SMEM_F16);

    conv_all<<<4096, 256>>>(x, Wq, Wk, Wv, Wo);

    gemm_f16<<<dim3(8, 32, 3), 256, SMEM_F16>>>(bq, bk, bv, nullptr, 0);

    dim3 agrid(SEQ / 64, NHEADS, BATCH);
    attn_tc<<<agrid, 128>>>();

    gemm_f16<<<dim3(8, 32, 1), 256, SMEM_F16>>>(bo, nullptr, nullptr, out, 1);
}